// round 5
// baseline (speedup 1.0000x reference)
#include <cuda_runtime.h>
#include <math.h>

#define B_   4
#define CIN  256
#define CQ   32
#define N3   13824   // 24^3
#define M3   1728    // 12^3
#define KC   32      // key chunk (attention)

using u64 = unsigned long long;

// ---- packed f32x2 helpers (sm_103a FFMA2 path) ----
__device__ __forceinline__ u64 pack2(float lo, float hi) {
    u64 r; asm("mov.b64 %0, {%1, %2};" : "=l"(r) : "f"(lo), "f"(hi)); return r;
}
__device__ __forceinline__ void unpack2(u64 v, float& lo, float& hi) {
    asm("mov.b64 {%0, %1}, %2;" : "=f"(lo), "=f"(hi) : "l"(v));
}
__device__ __forceinline__ u64 fma2(u64 a, u64 b, u64 c) {
    u64 d; asm("fma.rn.f32x2 %0, %1, %2, %3;" : "=l"(d) : "l"(a), "l"(b), "l"(c));
    return d;
}
__device__ __forceinline__ u64 mul2(u64 a, u64 b) {
    u64 d; asm("mul.rn.f32x2 %0, %1, %2;" : "=l"(d) : "l"(a), "l"(b));
    return d;
}

// Scratch (device globals). Layouts:
//   g_f, g_graw, g_hraw : [b][c][n]   (channel-major)
//   g_gp                : [b][c][m]   (channel-major, for score GEMM)
//   g_hp                : [b][m][c]   (key-major, for PV GEMM)
__device__ float g_f[B_ * CQ * N3];
__device__ float g_graw[B_ * CQ * N3];
__device__ float g_hraw[B_ * CQ * N3];
__device__ float g_gp[B_ * CQ * M3];
__device__ float g_hp[B_ * M3 * CQ];

// ---------------------------------------------------------------------------
// Projection: one W per gridDim.z (0=f,1=g,2=h). Block tile 32ch x 256pos,
// 128 threads, each owns 8ch x 8pos (register tile). FFMA2 inner loop.
// Output channel-major [b][c][n].
// ---------------------------------------------------------------------------
__global__ __launch_bounds__(128, 4) void proj_kernel(
    const float* __restrict__ x,
    const float* __restrict__ Wf,
    const float* __restrict__ Wg,
    const float* __restrict__ Wh)
{
    __shared__ float xs[32][256];   // 32 KB
    __shared__ float ws[32][32];    // 4 KB  [ci][c'] transposed chunk

    const int b   = blockIdx.y;
    const int z   = blockIdx.z;
    const int n0  = blockIdx.x * 256;
    const int tid = threadIdx.x;
    const int crow = tid >> 5;       // 0..3 -> c0 = crow*8
    const int pcol = tid & 31;       // 0..31 -> p0 = pcol*8
    const int c0 = crow * 8;
    const int p0 = pcol * 8;

    const float* W = (z == 0) ? Wf : (z == 1) ? Wg : Wh;
    float* dst = (z == 0) ? g_f : (z == 1) ? g_graw : g_hraw;

    u64 acc[32];                    // [c 0..7][ppair 0..3]
#pragma unroll
    for (int i = 0; i < 32; i++) acc[i] = 0ull;

    for (int cc0 = 0; cc0 < CIN; cc0 += 32) {
        __syncthreads();
        {
            const float4* xsrc = (const float4*)(x + ((size_t)b * CIN + cc0) * N3 + n0);
            float4* xdst = (float4*)&xs[0][0];
#pragma unroll
            for (int i = 0; i < 16; i++) {
                int idx = tid + i * 128;          // 0..2047 float4s
                int row = idx >> 6;
                int c4  = idx & 63;
                xdst[idx] = xsrc[(size_t)row * (N3 / 4) + c4];
            }
        }
#pragma unroll
        for (int i = 0; i < 8; i++) {
            int idx = tid + i * 128;
            int ci = idx >> 5, cp = idx & 31;
            ws[ci][cp] = W[cp * CIN + cc0 + ci];
        }
        __syncthreads();

#pragma unroll
        for (int ci = 0; ci < 32; ci++) {
            float4 wlo = *(const float4*)&ws[ci][c0];
            float4 whi = *(const float4*)&ws[ci][c0 + 4];
            const ulonglong2* xp = (const ulonglong2*)&xs[ci][p0];
            ulonglong2 x01 = xp[0];
            ulonglong2 x23 = xp[1];
            u64 xv[4] = { x01.x, x01.y, x23.x, x23.y };
            u64 wb[8];
            wb[0] = pack2(wlo.x, wlo.x); wb[1] = pack2(wlo.y, wlo.y);
            wb[2] = pack2(wlo.z, wlo.z); wb[3] = pack2(wlo.w, wlo.w);
            wb[4] = pack2(whi.x, whi.x); wb[5] = pack2(whi.y, whi.y);
            wb[6] = pack2(whi.z, whi.z); wb[7] = pack2(whi.w, whi.w);
#pragma unroll
            for (int c = 0; c < 8; c++) {
#pragma unroll
                for (int pp = 0; pp < 4; pp++) {
                    acc[c * 4 + pp] = fma2(wb[c], xv[pp], acc[c * 4 + pp]);
                }
            }
        }
    }

    // store channel-major
#pragma unroll
    for (int c = 0; c < 8; c++) {
        size_t base = ((size_t)(b * CQ + c0 + c)) * N3 + n0 + p0;
        ulonglong2* d = (ulonglong2*)(dst + base);
        d[0] = make_ulonglong2(acc[c * 4 + 0], acc[c * 4 + 1]);
        d[1] = make_ulonglong2(acc[c * 4 + 2], acc[c * 4 + 3]);
    }
}

// ---------------------------------------------------------------------------
// 2x2x2 max pool. Reads [b][c][n]; writes gp [b][c][m], hp [b][m][c].
// ---------------------------------------------------------------------------
__global__ void pool_kernel()
{
    int idx = blockIdx.x * 256 + threadIdx.x;
    const int total = B_ * CQ * M3;
    if (idx >= total) return;
    int m = idx % M3;
    int c = (idx / M3) % CQ;
    int b = idx / (M3 * CQ);
    int md = m / 144, mh = (m / 12) % 12, mw = m % 12;

    size_t cb = ((size_t)(b * CQ + c)) * N3;
    float gmax = -INFINITY, hmax = -INFINITY;
#pragma unroll
    for (int dd = 0; dd < 2; dd++)
#pragma unroll
        for (int dh = 0; dh < 2; dh++)
#pragma unroll
            for (int dw = 0; dw < 2; dw++) {
                int n = (2*md + dd) * 576 + (2*mh + dh) * 24 + (2*mw + dw);
                gmax = fmaxf(gmax, g_graw[cb + n]);
                hmax = fmaxf(hmax, g_hraw[cb + n]);
            }
    g_gp[idx] = gmax;                                   // [b][c][m]
    g_hp[((size_t)(b * M3 + m)) * CQ + c] = hmax;       // [b][m][c]
}

// ---------------------------------------------------------------------------
// Attention: block = 128 queries x all keys, two-phase register-tiled GEMMs.
// Phase A: S = F^T G chunk (128x32), exp -> ps smem. Thread: 8q x 4k.
// Phase B: O += H P^T.                Thread: 4c x 8q.
// Then Wv epilogue + residual (smem reuse for os/sWv).
// ---------------------------------------------------------------------------
#define FS_OFF  0        // 32*128 = 4096 floats
#define GS_OFF  4096     // 32*32  = 1024
#define HST_OFF 5120     // 32*32  = 1024
#define PS_OFF  6144     // 32*128 = 4096
#define LS_OFF  10240    // 128
#define OS_OFF  8192     // epilogue: 32*128 = 4096 (overlaps ps/ls, dead then)
// sWv at offset 0: 8192 floats (overlaps fs/gs/hst/ps, dead at epilogue)

__global__ __launch_bounds__(128, 4) void attn_kernel(
    const float* __restrict__ x,
    const float* __restrict__ Wv,
    const float* __restrict__ gamma_p,
    float* __restrict__ out)
{
    __shared__ float sm[12288];   // 48 KB

    const int b     = blockIdx.y;
    const int tid   = threadIdx.x;
    const int qbase = blockIdx.x * 128;
    const int qcol  = tid & 15;      // 0..15
    const int trow  = tid >> 4;      // 0..7 (krow in A, crow in B)
    const int q0    = qcol * 8;

    // load F tile: fs[c][q] (c-major)
    {
        const float* fsrc = g_f + ((size_t)(b * CQ)) * N3 + qbase;
#pragma unroll
        for (int i = 0; i < 32; i++) {
            int idx = tid + i * 128;
            int c = idx >> 7, q = idx & 127;
            sm[FS_OFF + idx] = fsrc[(size_t)c * N3 + q];
        }
    }

    u64 o2[16];                      // [c 0..3][qpair 0..3]
#pragma unroll
    for (int i = 0; i < 16; i++) o2[i] = 0ull;
    float l = 0.f;

    for (int kbase = 0; kbase < M3; kbase += KC) {
        __syncthreads();
        // stage gs[c][k] and hst[k][c]
        {
            const float* gsrc = g_gp + ((size_t)(b * CQ)) * M3 + kbase;
#pragma unroll
            for (int i = 0; i < 8; i++) {
                int idx = tid + i * 128;
                int c = idx >> 5, k = idx & 31;
                sm[GS_OFF + idx] = gsrc[(size_t)c * M3 + k];
            }
            const float4* hsrc = (const float4*)(g_hp + ((size_t)(b * M3 + kbase)) * CQ);
            float4* hdst = (float4*)&sm[HST_OFF];
#pragma unroll
            for (int i = 0; i < 2; i++) {
                hdst[tid + i * 128] = hsrc[tid + i * 128];
            }
        }
        __syncthreads();

        // ---- Phase A: scores S[8q x 4k] per thread ----
        {
            const int k0 = trow * 4;
            u64 s2[16];              // [k 0..3][qpair 0..3]
#pragma unroll
            for (int i = 0; i < 16; i++) s2[i] = 0ull;

#pragma unroll
            for (int ci = 0; ci < 32; ci++) {
                const ulonglong2* fp = (const ulonglong2*)&sm[FS_OFF + ci * 128 + q0];
                ulonglong2 f01 = fp[0];
                ulonglong2 f23 = fp[1];
                u64 fq[4] = { f01.x, f01.y, f23.x, f23.y };
                float4 gv = *(const float4*)&sm[GS_OFF + ci * 32 + k0];
                u64 gb[4];
                gb[0] = pack2(gv.x, gv.x); gb[1] = pack2(gv.y, gv.y);
                gb[2] = pack2(gv.z, gv.z); gb[3] = pack2(gv.w, gv.w);
#pragma unroll
                for (int k = 0; k < 4; k++) {
#pragma unroll
                    for (int qp = 0; qp < 4; qp++) {
                        s2[k * 4 + qp] = fma2(gb[k], fq[qp], s2[k * 4 + qp]);
                    }
                }
            }
            // exp + write ps[k][q]
#pragma unroll
            for (int k = 0; k < 4; k++) {
#pragma unroll
                for (int qp = 0; qp < 4; qp++) {
                    float sa, sb;
                    unpack2(s2[k * 4 + qp], sa, sb);
                    float ea = __expf(sa);
                    float eb = __expf(sb);
                    *(u64*)&sm[PS_OFF + (k0 + k) * 128 + q0 + 2 * qp] = pack2(ea, eb);
                }
            }
        }
        __syncthreads();

        // ---- l accumulation: thread owns q = tid ----
#pragma unroll
        for (int k = 0; k < KC; k++) l += sm[PS_OFF + k * 128 + tid];

        // ---- Phase B: O[4c x 8q] += H P^T ----
        {
            const int c0 = trow * 4;
#pragma unroll
            for (int k = 0; k < KC; k++) {
                float4 hv = *(const float4*)&sm[HST_OFF + k * 32 + c0];
                u64 hb[4];
                hb[0] = pack2(hv.x, hv.x); hb[1] = pack2(hv.y, hv.y);
                hb[2] = pack2(hv.z, hv.z); hb[3] = pack2(hv.w, hv.w);
                const ulonglong2* pp = (const ulonglong2*)&sm[PS_OFF + k * 128 + q0];
                ulonglong2 p01 = pp[0];
                ulonglong2 p23 = pp[1];
                u64 pq[4] = { p01.x, p01.y, p23.x, p23.y };
#pragma unroll
                for (int c = 0; c < 4; c++) {
#pragma unroll
                    for (int qp = 0; qp < 4; qp++) {
                        o2[c * 4 + qp] = fma2(hb[c], pq[qp], o2[c * 4 + qp]);
                    }
                }
            }
        }
    }

    // publish l, normalize
    __syncthreads();
    sm[LS_OFF + tid] = l;
    __syncthreads();
    {
        const int qg = q0;
#pragma unroll
        for (int qp = 0; qp < 4; qp++) {
            float l0 = sm[LS_OFF + qg + 2 * qp];
            float l1 = sm[LS_OFF + qg + 2 * qp + 1];
            u64 iv = pack2(1.0f / l0, 1.0f / l1);
#pragma unroll
            for (int c = 0; c < 4; c++) {
                o2[c * 4 + qp] = mul2(o2[c * 4 + qp], iv);
            }
        }
    }
    __syncthreads();   // ls consumed; safe to overwrite smem

    // write os[c][q] (normalized o), load sWv
    {
        const int c0 = trow * 4;
#pragma unroll
        for (int c = 0; c < 4; c++) {
#pragma unroll
            for (int qp = 0; qp < 4; qp++) {
                *(u64*)&sm[OS_OFF + (c0 + c) * 128 + q0 + 2 * qp] = o2[c * 4 + qp];
            }
        }
        const float4* wsrc = (const float4*)Wv;
        float4* wdst = (float4*)&sm[0];
#pragma unroll
        for (int i = 0; i < 16; i++) {
            wdst[tid + i * 128] = wsrc[tid + i * 128];
        }
    }
    __syncthreads();

    // Wv epilogue + residual: thread owns q = tid
    {
        u64 oc2[16];
#pragma unroll
        for (int i = 0; i < 16; i++) {
            oc2[i] = pack2(sm[OS_OFF + (2 * i) * 128 + tid],
                           sm[OS_OFF + (2 * i + 1) * 128 + tid]);
        }
        const float gma = *gamma_p;
        const int q = qbase + tid;
        size_t xb = (size_t)b * CIN * N3 + q;
#pragma unroll 4
        for (int cc = 0; cc < CIN; cc++) {
            const ulonglong2* wp = (const ulonglong2*)&sm[cc * CQ];
            u64 ea = 0ull, eb = 0ull;
#pragma unroll
            for (int c = 0; c < 8; c++) {
                ulonglong2 w = wp[c];
                ea = fma2(oc2[2 * c + 0], w.x, ea);
                eb = fma2(oc2[2 * c + 1], w.y, eb);
            }
            float a0, a1, b0, b1;
            unpack2(ea, a0, a1);
            unpack2(eb, b0, b1);
            float s = (a0 + a1) + (b0 + b1);
            size_t o = xb + (size_t)cc * N3;
            out[o] = fmaf(gma, s, x[o]);
        }
    }
}

// ---------------------------------------------------------------------------
extern "C" void kernel_launch(void* const* d_in, const int* in_sizes, int n_in,
                              void* d_out, int out_size)
{
    const float* x     = (const float*)d_in[0];
    const float* Wf    = (const float*)d_in[1];
    const float* Wg    = (const float*)d_in[2];
    const float* Wh    = (const float*)d_in[3];
    const float* Wv    = (const float*)d_in[4];
    const float* gamma = (const float*)d_in[5];
    float* out = (float*)d_out;

    dim3 pgrid(N3 / 256, B_, 3);
    proj_kernel<<<pgrid, 128>>>(x, Wf, Wg, Wh);

    int ptotal = B_ * CQ * M3;
    pool_kernel<<<(ptotal + 255) / 256, 256>>>();

    dim3 agrid(N3 / 128, B_);
    attn_kernel<<<agrid, 128>>>(x, Wv, gamma, out);
}

// round 8
// speedup vs baseline: 1.8361x; 1.8361x over previous
#include <cuda_runtime.h>
#include <cuda_bf16.h>
#include <math.h>
#include <stdint.h>

#define B_   4
#define CIN  256
#define CQ   32
#define N3   13824   // 24^3
#define M3   1728    // 12^3
#define KT   64      // keys per tile
#define NKT  (M3/KT) // 27
#define QT   128     // queries per CTA

using u64 = unsigned long long;

// ---- packed f32x2 helpers (scalar proj path) ----
__device__ __forceinline__ u64 pack2(float lo, float hi) {
    u64 r; asm("mov.b64 %0, {%1, %2};" : "=l"(r) : "f"(lo), "f"(hi)); return r;
}
__device__ __forceinline__ u64 fma2(u64 a, u64 b, u64 c) {
    u64 d; asm("fma.rn.f32x2 %0, %1, %2, %3;" : "=l"(d) : "l"(a), "l"(b), "l"(c));
    return d;
}

// ---- warp MMA helpers (baseline PTX, sm_80+ features, no 'a'-arch needed) ----
__device__ __forceinline__ uint32_t smem_to_u32(const void* p) {
    uint32_t a;
    asm("{ .reg .u64 t; cvta.to.shared.u64 t, %1; cvt.u32.u64 %0, t; }" : "=r"(a) : "l"(p));
    return a;
}
__device__ __forceinline__ void ldsm4(uint32_t* r, uint32_t a) {
    asm volatile("ldmatrix.sync.aligned.m8n8.x4.shared.b16 {%0,%1,%2,%3}, [%4];"
        : "=r"(r[0]), "=r"(r[1]), "=r"(r[2]), "=r"(r[3]) : "r"(a));
}
__device__ __forceinline__ void ldsm2(uint32_t* r, uint32_t a) {
    asm volatile("ldmatrix.sync.aligned.m8n8.x2.shared.b16 {%0,%1}, [%2];"
        : "=r"(r[0]), "=r"(r[1]) : "r"(a));
}
__device__ __forceinline__ void mmabf(float* c, const uint32_t* a, const uint32_t* b) {
    asm volatile("mma.sync.aligned.m16n8k16.row.col.f32.bf16.bf16.f32 "
        "{%0,%1,%2,%3}, {%4,%5,%6,%7}, {%8,%9}, {%0,%1,%2,%3};"
        : "+f"(c[0]), "+f"(c[1]), "+f"(c[2]), "+f"(c[3])
        : "r"(a[0]), "r"(a[1]), "r"(a[2]), "r"(a[3]), "r"(b[0]), "r"(b[1]));
}

// split float pair -> bf16 hi pair + lo pair (each 4B store)
__device__ __forceinline__ void split_store(char* hi_p, char* lo_p, float a, float b) {
    __nv_bfloat16 ha = __float2bfloat16(a);
    __nv_bfloat16 hb = __float2bfloat16(b);
    float la = a - __bfloat162float(ha);
    float lb = b - __bfloat162float(hb);
    __nv_bfloat162 h; h.x = ha; h.y = hb;
    __nv_bfloat162 l; l.x = __float2bfloat16(la); l.y = __float2bfloat16(lb);
    *(__nv_bfloat162*)hi_p = h;
    *(__nv_bfloat162*)lo_p = l;
}

// Scratch (device globals)
__device__ float g_f[B_ * N3 * CQ];      // [b][n][32]
__device__ float g_graw[B_ * N3 * CQ];   // [b][n][32]
__device__ float g_hraw[B_ * N3 * CQ];   // [b][n][32]
__device__ float g_gp[B_ * M3 * CQ];     // [b][m][32]
__device__ float g_hpT[B_ * CQ * M3];    // [b][c][m]

// smem layout (bytes); strides in bf16 elements
#define FSTR 40
#define GSTR 40
#define HSTR 72
#define PSTR 72
#define OSTR 40
#define WSTR 32
#define FHI 0
#define FLO 10240
#define GHI 20480
#define GLO 25600
#define HHI 30720
#define HLO 35328
#define PHI 39936
#define PLO 58368
#define SMEM_BYTES 76800
// reuse after key loop:
#define OHI 0
#define OLO 10240
#define WVH 39936
#define WVL 56320

// ---------------------------------------------------------------------------
// Projection (scalar FFMA2, r2 version): one W per gridDim.z. Output [b][n][32].
// ---------------------------------------------------------------------------
__global__ __launch_bounds__(128) void proj_kernel(
    const float* __restrict__ x,
    const float* __restrict__ Wf,
    const float* __restrict__ Wg,
    const float* __restrict__ Wh)
{
    __shared__ float xs[32][256];
    __shared__ float ws[32][32];

    const int b   = blockIdx.y;
    const int z   = blockIdx.z;
    const int n0  = blockIdx.x * 256;
    const int tid = threadIdx.x;

    const float* W = (z == 0) ? Wf : (z == 1) ? Wg : Wh;
    float* dst = (z == 0) ? g_f : (z == 1) ? g_graw : g_hraw;

    u64 acc0[16], acc1[16];
#pragma unroll
    for (int i = 0; i < 16; i++) { acc0[i] = 0ull; acc1[i] = 0ull; }

    for (int cc0 = 0; cc0 < CIN; cc0 += 32) {
        __syncthreads();
        {
            const float4* xsrc = (const float4*)(x + ((size_t)b * CIN + cc0) * N3 + n0);
            float4* xdst = (float4*)&xs[0][0];
#pragma unroll
            for (int i = 0; i < 16; i++) {
                int idx = tid + i * 128;
                int row = idx >> 6;
                int c4  = idx & 63;
                xdst[idx] = xsrc[(size_t)row * (N3 / 4) + c4];
            }
        }
#pragma unroll
        for (int i = 0; i < 8; i++) {
            int idx = tid + i * 128;
            int ci = idx >> 5, cp = idx & 31;
            ws[ci][cp] = W[cp * CIN + cc0 + ci];
        }
        __syncthreads();

#pragma unroll
        for (int ci = 0; ci < 32; ci++) {
            float x0 = xs[ci][tid];
            float x1 = xs[ci][tid + 128];
            u64 xv0 = pack2(x0, x0);
            u64 xv1 = pack2(x1, x1);
            const ulonglong2* wp = (const ulonglong2*)&ws[ci][0];
#pragma unroll
            for (int c = 0; c < 8; c++) {
                ulonglong2 w = wp[c];
                acc0[2*c + 0] = fma2(xv0, w.x, acc0[2*c + 0]);
                acc0[2*c + 1] = fma2(xv0, w.y, acc0[2*c + 1]);
                acc1[2*c + 0] = fma2(xv1, w.x, acc1[2*c + 0]);
                acc1[2*c + 1] = fma2(xv1, w.y, acc1[2*c + 1]);
            }
        }
    }

    {
        ulonglong2* d0 = (ulonglong2*)(dst + ((size_t)b * N3 + n0 + tid) * CQ);
        ulonglong2* d1 = (ulonglong2*)(dst + ((size_t)b * N3 + n0 + 128 + tid) * CQ);
#pragma unroll
        for (int c = 0; c < 8; c++) {
            d0[c] = make_ulonglong2(acc0[2*c], acc0[2*c + 1]);
            d1[c] = make_ulonglong2(acc1[2*c], acc1[2*c + 1]);
        }
    }
}

// ---------------------------------------------------------------------------
// 2x2x2 max pool: [b][n][32] -> g_gp [b][m][32], g_hpT [b][c][m]
// ---------------------------------------------------------------------------
__global__ void pool_kernel()
{
    int idx = blockIdx.x * 256 + threadIdx.x;
    const int total = B_ * M3 * CQ;
    if (idx >= total) return;
    int c = idx & 31;
    int m = (idx >> 5) % M3;
    int b = idx / (M3 * CQ);
    int md = m / 144, mh = (m / 12) % 12, mw = m % 12;

    float gmax = -INFINITY, hmax = -INFINITY;
#pragma unroll
    for (int dd = 0; dd < 2; dd++)
#pragma unroll
        for (int dh = 0; dh < 2; dh++)
#pragma unroll
            for (int dw = 0; dw < 2; dw++) {
                int n = (2*md + dd) * 576 + (2*mh + dh) * 24 + (2*mw + dw);
                size_t o = ((size_t)b * N3 + n) * CQ + c;
                gmax = fmaxf(gmax, g_graw[o]);
                hmax = fmaxf(hmax, g_hraw[o]);
            }
    g_gp[idx] = gmax;                                  // [b][m][32]
    g_hpT[((size_t)(b * CQ + c)) * M3 + m] = hmax;     // [b][c][m]
}

// ---------------------------------------------------------------------------
// Fused attention via mma.sync bf16 (2-way split, 3-term products).
// CTA = 128 queries, 4 warps; warp w owns query rows 32w..32w+31.
// ---------------------------------------------------------------------------
__global__ __launch_bounds__(128) void attn_mma_kernel(
    const float* __restrict__ x,
    const float* __restrict__ Wv,
    const float* __restrict__ gamma_p,
    float* __restrict__ out)
{
    extern __shared__ __align__(128) char sm[];
    const uint32_t smb = smem_to_u32(sm);
    const int tid  = threadIdx.x;
    const int w    = tid >> 5;
    const int lane = tid & 31;
    const int b = blockIdx.y;
    const int qbase = blockIdx.x * QT;

    const float gma = *gamma_p;

    // ldmatrix lane address components
    const int a_r = lane & 15;               // x4: row within 16
    const int a_c = (lane >> 4) << 3;        // x4: col 0 or 8
    const int b_r = lane & 7;                // x2: row within 8
    const int b_c = ((lane >> 3) & 1) << 3;  // x2: col 0 or 8

    // ---- load F tile: thread = row ----
    {
        const float4* src = (const float4*)(g_f + ((size_t)(b * N3 + qbase + tid)) * CQ);
#pragma unroll
        for (int i = 0; i < 8; i++) {
            float4 v = src[i];
            int c = i * 4;
            split_store(sm + FHI + (tid * FSTR + c) * 2, sm + FLO + (tid * FSTR + c) * 2, v.x, v.y);
            split_store(sm + FHI + (tid * FSTR + c + 2) * 2, sm + FLO + (tid * FSTR + c + 2) * 2, v.z, v.w);
        }
    }

    float oacc[2][4][4];
#pragma unroll
    for (int rt = 0; rt < 2; rt++)
#pragma unroll
        for (int n = 0; n < 4; n++)
#pragma unroll
            for (int i = 0; i < 4; i++) oacc[rt][n][i] = 0.f;
    float lpart[4] = {0.f, 0.f, 0.f, 0.f};

    const int asel[3] = {0, 1, 0};   // hi, lo, hi
    const int bsel[3] = {0, 0, 1};   // hi, hi, lo

    for (int kt = 0; kt < NKT; kt++) {
        const int kb = kt * KT;
        __syncthreads();   // previous iter's ldmatrix reads done before overwrite

        // load G tile (64 keys x 32 ch): thread -> (row = tid&63, half = tid>>6)
        {
            int row = tid & 63, half = tid >> 6;
            const float4* src = (const float4*)(g_gp + ((size_t)(b * M3 + kb + row)) * CQ + 16 * half);
#pragma unroll
            for (int i = 0; i < 4; i++) {
                float4 v = src[i];
                int c = 16 * half + i * 4;
                split_store(sm + GHI + (row * GSTR + c) * 2, sm + GLO + (row * GSTR + c) * 2, v.x, v.y);
                split_store(sm + GHI + (row * GSTR + c + 2) * 2, sm + GLO + (row * GSTR + c + 2) * 2, v.z, v.w);
            }
        }
        // load H tile (32 ch x 64 keys): thread -> (c = tid&31, j0 = 16*(tid>>5))
        {
            int c = tid & 31, j0 = (tid >> 5) * 16;
            const float4* src = (const float4*)(g_hpT + ((size_t)(b * CQ + c)) * M3 + kb + j0);
#pragma unroll
            for (int i = 0; i < 4; i++) {
                float4 v = src[i];
                int j = j0 + i * 4;
                split_store(sm + HHI + (c * HSTR + j) * 2, sm + HLO + (c * HSTR + j) * 2, v.x, v.y);
                split_store(sm + HHI + (c * HSTR + j + 2) * 2, sm + HLO + (c * HSTR + j + 2) * 2, v.z, v.w);
            }
        }
        __syncthreads();

        // ---- S GEMM: sacc[rt][n] = F(128x32) . G(64x32)^T, 3 split terms ----
        float sacc[2][8][4];
#pragma unroll
        for (int rt = 0; rt < 2; rt++)
#pragma unroll
            for (int n = 0; n < 8; n++)
#pragma unroll
                for (int i = 0; i < 4; i++) sacc[rt][n][i] = 0.f;

#pragma unroll
        for (int t = 0; t < 3; t++) {
            const uint32_t fb = smb + (asel[t] ? FLO : FHI);
            const uint32_t gb = smb + (bsel[t] ? GLO : GHI);
#pragma unroll
            for (int ks = 0; ks < 2; ks++) {
                const int k0 = 16 * ks;
                uint32_t af[2][4];
#pragma unroll
                for (int rt = 0; rt < 2; rt++)
                    ldsm4(af[rt], fb + ((32 * w + 16 * rt + a_r) * FSTR + k0 + a_c) * 2);
#pragma unroll
                for (int n = 0; n < 8; n++) {
                    uint32_t bf2[2];
                    ldsm2(bf2, gb + ((8 * n + b_r) * GSTR + k0 + b_c) * 2);
                    mmabf(sacc[0][n], af[0], bf2);
                    mmabf(sacc[1][n], af[1], bf2);
                }
            }
        }

        // ---- softmax: exp in regs, accumulate l partials, split-store P ----
#pragma unroll
        for (int rt = 0; rt < 2; rt++) {
            int row0 = 32 * w + 16 * rt + (lane >> 2);
#pragma unroll
            for (int n = 0; n < 8; n++) {
                float e0 = __expf(sacc[rt][n][0]);
                float e1 = __expf(sacc[rt][n][1]);
                float e2 = __expf(sacc[rt][n][2]);
                float e3 = __expf(sacc[rt][n][3]);
                lpart[rt * 2 + 0] += e0 + e1;
                lpart[rt * 2 + 1] += e2 + e3;
                int col = 8 * n + 2 * (lane & 3);
                split_store(sm + PHI + (row0 * PSTR + col) * 2,
                            sm + PLO + (row0 * PSTR + col) * 2, e0, e1);
                split_store(sm + PHI + ((row0 + 8) * PSTR + col) * 2,
                            sm + PLO + ((row0 + 8) * PSTR + col) * 2, e2, e3);
            }
        }
        __syncwarp();   // P rows are warp-private; order STS -> LDSM

        // ---- PV GEMM: O += P(128x64) . H(32x64)^T, 3 split terms ----
#pragma unroll
        for (int t = 0; t < 3; t++) {
            const uint32_t pb = smb + (asel[t] ? PLO : PHI);
            const uint32_t hb = smb + (bsel[t] ? HLO : HHI);
#pragma unroll
            for (int ks = 0; ks < 4; ks++) {
                const int k0 = 16 * ks;
                uint32_t af[2][4];
#pragma unroll
                for (int rt = 0; rt < 2; rt++)
                    ldsm4(af[rt], pb + ((32 * w + 16 * rt + a_r) * PSTR + k0 + a_c) * 2);
#pragma unroll
                for (int n = 0; n < 4; n++) {
                    uint32_t bf2[2];
                    ldsm2(bf2, hb + ((8 * n + b_r) * HSTR + k0 + b_c) * 2);
                    mmabf(oacc[0][n], af[0], bf2);
                    mmabf(oacc[1][n], af[1], bf2);
                }
            }
        }
    }

    // ---- reduce l across the 4 lanes sharing a row; normalize O ----
    float inv[4];
#pragma unroll
    for (int i = 0; i < 4; i++) {
        float v = lpart[i];
        v += __shfl_xor_sync(0xFFFFFFFFu, v, 1);
        v += __shfl_xor_sync(0xFFFFFFFFu, v, 2);
        inv[i] = 1.0f / v;
    }

    __syncthreads();   // all warps done reading F before O overwrites it

    // store normalized O (bf16 split) into F region; load Wv into P region
#pragma unroll
    for (int rt = 0; rt < 2; rt++) {
        int row0 = 32 * w + 16 * rt + (lane >> 2);
#pragma unroll
        for (int n = 0; n < 4; n++) {
            float v0 = oacc[rt][n][0] * inv[rt * 2 + 0];
            float v1 = oacc[rt][n][1] * inv[rt * 2 + 0];
            float v2 = oacc[rt][n][2] * inv[rt * 2 + 1];
            float v3 = oacc[rt][n][3] * inv[rt * 2 + 1];
            int col = 8 * n + 2 * (lane & 3);
            split_store(sm + OHI + (row0 * OSTR + col) * 2,
                        sm + OLO + (row0 * OSTR + col) * 2, v0, v1);
            split_store(sm + OHI + ((row0 + 8) * OSTR + col) * 2,
                        sm + OLO + ((row0 + 8) * OSTR + col) * 2, v2, v3);
        }
    }
    {
#pragma unroll
        for (int h = 0; h < 2; h++) {
            int r = tid + 128 * h;
            const float4* src = (const float4*)(Wv + r * CQ);
#pragma unroll
            for (int i = 0; i < 8; i++) {
                float4 v = src[i];
                int c = i * 4;
                split_store(sm + WVH + (r * WSTR + c) * 2, sm + WVL + (r * WSTR + c) * 2, v.x, v.y);
                split_store(sm + WVH + (r * WSTR + c + 2) * 2, sm + WVL + (r * WSTR + c + 2) * 2, v.z, v.w);
            }
        }
    }
    __syncthreads();

    // ---- Out = O(128x32) . Wv(256x32)^T in 4 chunks of 64 cols ----
#pragma unroll 1
    for (int ch = 0; ch < 4; ch++) {
        float wacc[2][8][4];
#pragma unroll
        for (int rt = 0; rt < 2; rt++)
#pragma unroll
            for (int n = 0; n < 8; n++)
#pragma unroll
                for (int i = 0; i < 4; i++) wacc[rt][n][i] = 0.f;

#pragma unroll
        for (int t = 0; t < 3; t++) {
            const uint32_t ob = smb + (asel[t] ? OLO : OHI);
            const uint32_t wb = smb + (bsel[t] ? WVL : WVH);
#pragma unroll
            for (int ks = 0; ks < 2; ks++) {
                const int k0 = 16 * ks;
                uint32_t af[2][4];
#pragma unroll
                for (int rt = 0; rt < 2; rt++)
                    ldsm4(af[rt], ob + ((32 * w + 16 * rt + a_r) * OSTR + k0 + a_c) * 2);
#pragma unroll
                for (int n = 0; n < 8; n++) {
                    uint32_t bf2[2];
                    ldsm2(bf2, wb + ((ch * 64 + 8 * n + b_r) * WSTR + k0 + b_c) * 2);
                    mmabf(wacc[0][n], af[0], bf2);
                    mmabf(wacc[1][n], af[1], bf2);
                }
            }
        }

        // write out + residual
#pragma unroll
        for (int rt = 0; rt < 2; rt++) {
            int q0 = qbase + 32 * w + 16 * rt + (lane >> 2);
#pragma unroll
            for (int n = 0; n < 8; n++) {
                int cc = ch * 64 + 8 * n + 2 * (lane & 3);
                size_t o0 = ((size_t)(b * CIN + cc)) * N3 + q0;
                out[o0]          = fmaf(gma, wacc[rt][n][0], x[o0]);
                out[o0 + N3]     = fmaf(gma, wacc[rt][n][1], x[o0 + N3]);
                out[o0 + 8]      = fmaf(gma, wacc[rt][n][2], x[o0 + 8]);
                out[o0 + N3 + 8] = fmaf(gma, wacc[rt][n][3], x[o0 + N3 + 8]);
            }
        }
    }
}

// ---------------------------------------------------------------------------
extern "C" void kernel_launch(void* const* d_in, const int* in_sizes, int n_in,
                              void* d_out, int out_size)
{
    const float* x     = (const float*)d_in[0];
    const float* Wf    = (const float*)d_in[1];
    const float* Wg    = (const float*)d_in[2];
    const float* Wh    = (const float*)d_in[3];
    const float* Wv    = (const float*)d_in[4];
    const float* gamma = (const float*)d_in[5];
    float* out = (float*)d_out;

    static bool attr_set = false;
    if (!attr_set) {
        cudaFuncSetAttribute(attn_mma_kernel,
                             cudaFuncAttributeMaxDynamicSharedMemorySize, SMEM_BYTES);
        attr_set = true;
    }

    dim3 pgrid(N3 / 256, B_, 3);
    proj_kernel<<<pgrid, 128>>>(x, Wf, Wg, Wh);

    int ptotal = B_ * M3 * CQ;
    pool_kernel<<<(ptotal + 255) / 256, 256>>>();

    dim3 agrid(N3 / QT, B_);
    attn_mma_kernel<<<agrid, 128, SMEM_BYTES>>>(x, Wv, gamma, out);
}

// round 9
// speedup vs baseline: 2.6239x; 1.4291x over previous
#include <cuda_runtime.h>
#include <cuda_bf16.h>
#include <math.h>
#include <stdint.h>

#define B_   4
#define CIN  256
#define CQ   32
#define N3   13824   // 24^3
#define M3   1728    // 12^3
#define KT   64      // keys per tile
#define NKT  (M3/KT) // 27
#define QT   128     // queries per CTA

// ---- warp MMA helpers (baseline PTX, sm_75/80+ features) ----
__device__ __forceinline__ uint32_t smem_to_u32(const void* p) {
    uint32_t a;
    asm("{ .reg .u64 t; cvta.to.shared.u64 t, %1; cvt.u32.u64 %0, t; }" : "=r"(a) : "l"(p));
    return a;
}
__device__ __forceinline__ void ldsm4(uint32_t* r, uint32_t a) {
    asm volatile("ldmatrix.sync.aligned.m8n8.x4.shared.b16 {%0,%1,%2,%3}, [%4];"
        : "=r"(r[0]), "=r"(r[1]), "=r"(r[2]), "=r"(r[3]) : "r"(a));
}
__device__ __forceinline__ void ldsm2(uint32_t* r, uint32_t a) {
    asm volatile("ldmatrix.sync.aligned.m8n8.x2.shared.b16 {%0,%1}, [%2];"
        : "=r"(r[0]), "=r"(r[1]) : "r"(a));
}
__device__ __forceinline__ void ldsm2t(uint32_t* r, uint32_t a) {
    asm volatile("ldmatrix.sync.aligned.m8n8.x2.trans.shared.b16 {%0,%1}, [%2];"
        : "=r"(r[0]), "=r"(r[1]) : "r"(a));
}
__device__ __forceinline__ void mmabf(float* c, const uint32_t* a, const uint32_t* b) {
    asm volatile("mma.sync.aligned.m16n8k16.row.col.f32.bf16.bf16.f32 "
        "{%0,%1,%2,%3}, {%4,%5,%6,%7}, {%8,%9}, {%0,%1,%2,%3};"
        : "+f"(c[0]), "+f"(c[1]), "+f"(c[2]), "+f"(c[3])
        : "r"(a[0]), "r"(a[1]), "r"(a[2]), "r"(a[3]), "r"(b[0]), "r"(b[1]));
}
__device__ __forceinline__ float ex2f(float x) {
    float r; asm("ex2.approx.ftz.f32 %0, %1;" : "=f"(r) : "f"(x)); return r;
}
// split (a,b) -> bf16x2 hi reg + bf16x2 lo reg
__device__ __forceinline__ void splitpair(float a, float b, uint32_t& hi, uint32_t& lo) {
    __nv_bfloat162 h = __floats2bfloat162_rn(a, b);   // .x = a (low half)
    float ra = a - __bfloat162float(h.x);
    float rb = b - __bfloat162float(h.y);
    __nv_bfloat162 l = __floats2bfloat162_rn(ra, rb);
    hi = *(uint32_t*)&h;
    lo = *(uint32_t*)&l;
}

// Scratch (device globals). Layouts:
//   g_f, g_graw, g_hraw : [b][c][n]  (channel-major)
//   g_gp                : [b][m][c]
//   g_hpT               : [b][c][m]
__device__ float g_f[B_ * CQ * N3];
__device__ float g_graw[B_ * CQ * N3];
__device__ float g_hraw[B_ * CQ * N3];
__device__ float g_gp[B_ * M3 * CQ];
__device__ float g_hpT[B_ * CQ * M3];

// ---------------------------------------------------------------------------
// Projection via mma.sync: out[96, n] = W[96,256] x x[256, n] (3-term split).
// CTA: 128 positions, all 96 output channels. A = W (row-major), B = x chunk
// [k][n] consumed via ldmatrix.trans. Output channel-major [b][c][n].
// ---------------------------------------------------------------------------
#define PXSTR 272   // bytes per x row (128 bf16 + 8 pad)
#define PWSTR 80    // bytes per W row (32 bf16 + 8 pad)
#define PXHI 0
#define PXLO 8704
#define PWHI 17408
#define PWLO 25088
#define PSMEM 32768

__global__ __launch_bounds__(128) void proj_mma_kernel(
    const float* __restrict__ x,
    const float* __restrict__ Wf,
    const float* __restrict__ Wg,
    const float* __restrict__ Wh)
{
    __shared__ __align__(16) char sm[PSMEM];
    const uint32_t smb = smem_to_u32(sm);
    const int tid  = threadIdx.x;
    const int w    = tid >> 5;
    const int lane = tid & 31;
    const int b    = blockIdx.y;
    const int n0   = blockIdx.x * 128;

    const int a_r = lane & 15;
    const int a_c = (lane >> 4) << 3;
    const int tr  = (lane & 7) + 8 * ((lane >> 3) & 1);  // trans row id (lanes 0..15 used)

    float oacc[96];
#pragma unroll
    for (int i = 0; i < 96; i++) oacc[i] = 0.f;

    for (int cc0 = 0; cc0 < CIN; cc0 += 32) {
        __syncthreads();
        // stage x chunk [32 k][128 n] split hi/lo
#pragma unroll
        for (int i = 0; i < 8; i++) {
            int idx = tid + i * 128;        // 0..1023 float4 units
            int row = idx >> 5;
            int seg = idx & 31;
            float4 v = *(const float4*)(x + ((size_t)(b * CIN + cc0 + row)) * N3 + n0 + 4 * seg);
            uint32_t h0, l0, h1, l1;
            splitpair(v.x, v.y, h0, l0);
            splitpair(v.z, v.w, h1, l1);
            *(uint2*)(sm + PXHI + row * PXSTR + 8 * seg) = make_uint2(h0, h1);
            *(uint2*)(sm + PXLO + row * PXSTR + 8 * seg) = make_uint2(l0, l1);
        }
        // stage W chunk [96 rows][32 k] split hi/lo (rows 0-31 Wf, 32-63 Wg, 64-95 Wh)
#pragma unroll
        for (int i = 0; i < 6; i++) {
            int idx = tid + i * 128;        // 0..767 float4 units
            int row = idx >> 3;
            int seg = idx & 7;
            const float* Wsrc = (row < 32) ? Wf : ((row < 64) ? Wg : Wh);
            float4 v = *(const float4*)(Wsrc + (row & 31) * CIN + cc0 + 4 * seg);
            uint32_t h0, l0, h1, l1;
            splitpair(v.x, v.y, h0, l0);
            splitpair(v.z, v.w, h1, l1);
            *(uint2*)(sm + PWHI + row * PWSTR + 8 * seg) = make_uint2(h0, h1);
            *(uint2*)(sm + PWLO + row * PWSTR + 8 * seg) = make_uint2(l0, l1);
        }
        __syncthreads();

#pragma unroll
        for (int ks = 0; ks < 2; ks++) {
            // B frags from x via ldsm2.trans: warp w owns positions 32w..32w+31
            uint32_t bh[4][2], bl[4][2];
#pragma unroll
            for (int nt = 0; nt < 4; nt++) {
                uint32_t addr = smb + PXHI + (16 * ks + tr) * PXSTR + (32 * w + 8 * nt) * 2;
                ldsm2t(bh[nt], addr);
                ldsm2t(bl[nt], addr + (PXLO - PXHI));
            }
#pragma unroll
            for (int mt = 0; mt < 6; mt++) {
                uint32_t ah[4], al[4];
                uint32_t wadr = smb + PWHI + (16 * mt + a_r) * PWSTR + (16 * ks + a_c) * 2;
                ldsm4(ah, wadr);
                ldsm4(al, wadr + (PWLO - PWHI));
#pragma unroll
                for (int nt = 0; nt < 4; nt++) {
                    float* c = &oacc[(mt * 4 + nt) * 4];
                    mmabf(c, ah, bh[nt]);
                    mmabf(c, al, bh[nt]);
                    mmabf(c, ah, bl[nt]);
                }
            }
        }
    }

    // store: C[m=outch][n=pos], float2 per fragment row
    const int gid = lane >> 2;
    const int qid = lane & 3;
#pragma unroll
    for (int mt = 0; mt < 6; mt++) {
        float* dst = (mt < 2) ? g_f : ((mt < 4) ? g_graw : g_hraw);
        int ch = ((16 * mt) & 31) + gid;
#pragma unroll
        for (int nt = 0; nt < 4; nt++) {
            const float* c = &oacc[(mt * 4 + nt) * 4];
            int pos = n0 + 32 * w + 8 * nt + 2 * qid;
            size_t r0 = ((size_t)(b * CQ + ch)) * N3 + pos;
            size_t r1 = ((size_t)(b * CQ + ch + 8)) * N3 + pos;
            *(float2*)(dst + r0) = make_float2(c[0], c[1]);
            *(float2*)(dst + r1) = make_float2(c[2], c[3]);
        }
    }
}

// ---------------------------------------------------------------------------
// 2x2x2 max pool: [b][c][n] -> g_gp [b][m][c], g_hpT [b][c][m]
// ---------------------------------------------------------------------------
__global__ void pool_kernel()
{
    int idx = blockIdx.x * 256 + threadIdx.x;
    const int total = B_ * CQ * M3;
    if (idx >= total) return;
    int m = idx % M3;
    int c = (idx / M3) % CQ;
    int b = idx / (M3 * CQ);
    int md = m / 144, mh = (m / 12) % 12, mw = m % 12;

    const float* gbase = g_graw + ((size_t)(b * CQ + c)) * N3;
    const float* hbase = g_hraw + ((size_t)(b * CQ + c)) * N3;
    int n00 = (2 * md) * 576 + (2 * mh) * 24 + 2 * mw;

    float gmax = -INFINITY, hmax = -INFINITY;
#pragma unroll
    for (int dd = 0; dd < 2; dd++)
#pragma unroll
        for (int dh = 0; dh < 2; dh++) {
            int n = n00 + dd * 576 + dh * 24;
            float2 gv = *(const float2*)(gbase + n);
            float2 hv = *(const float2*)(hbase + n);
            gmax = fmaxf(gmax, fmaxf(gv.x, gv.y));
            hmax = fmaxf(hmax, fmaxf(hv.x, hv.y));
        }
    g_gp[((size_t)(b * M3 + m)) * CQ + c] = gmax;
    g_hpT[((size_t)(b * CQ + c)) * M3 + m] = hmax;
}

// ---------------------------------------------------------------------------
// Fused attention, register-resident P and O fragments.
// smem: F[128][40] hi/lo, G[64][40] hi/lo, H[32][72] hi/lo; Wv overlays after.
// ---------------------------------------------------------------------------
#define FSTR 40
#define GSTR 40
#define HSTR 72
#define WSTR 40
#define FHI 0
#define FLO 10240
#define GHI 20480
#define GLO 25600
#define HHI 30720
#define HLO 35328
#define WVH 0
#define WVL 20480
#define ASMEM 40960

__global__ __launch_bounds__(128) void attn_mma_kernel(
    const float* __restrict__ x,
    const float* __restrict__ Wv,
    const float* __restrict__ gamma_p,
    float* __restrict__ out)
{
    __shared__ __align__(16) char sm[ASMEM];
    const uint32_t smb = smem_to_u32(sm);
    const int tid  = threadIdx.x;
    const int w    = tid >> 5;
    const int lane = tid & 31;
    const int b = blockIdx.y;
    const int qbase = blockIdx.x * QT;

    const float gma = *gamma_p;
    const float LOG2E = 1.4426950408889634f;

    const int a_r = lane & 15;
    const int a_c = (lane >> 4) << 3;
    const int b_r = lane & 7;
    const int b_c = ((lane >> 3) & 1) << 3;

    // ---- load F tile from [b][c][n], fold log2e ----
    {
        const float* fb = g_f + (size_t)b * CQ * N3 + qbase + tid;
#pragma unroll
        for (int cp = 0; cp < 16; cp++) {
            float fa = fb[(size_t)(2 * cp) * N3] * LOG2E;
            float fc = fb[(size_t)(2 * cp + 1) * N3] * LOG2E;
            uint32_t h, l;
            splitpair(fa, fc, h, l);
            *(uint32_t*)(sm + FHI + (tid * FSTR + 2 * cp) * 2) = h;
            *(uint32_t*)(sm + FLO + (tid * FSTR + 2 * cp) * 2) = l;
        }
    }

    float oacc[2][4][4];
#pragma unroll
    for (int rt = 0; rt < 2; rt++)
#pragma unroll
        for (int n = 0; n < 4; n++)
#pragma unroll
            for (int i = 0; i < 4; i++) oacc[rt][n][i] = 0.f;
    float lpart[4] = {0.f, 0.f, 0.f, 0.f};

    for (int kt = 0; kt < NKT; kt++) {
        const int kb = kt * KT;
        __syncthreads();
        // stage G (64 keys x 32 ch) from g_gp [b][m][c]
        {
            int row = tid & 63, half = tid >> 6;
            const float4* src = (const float4*)(g_gp + ((size_t)(b * M3 + kb + row)) * CQ + 16 * half);
#pragma unroll
            for (int i = 0; i < 4; i++) {
                float4 v = src[i];
                int c = 16 * half + i * 4;
                uint32_t h0, l0, h1, l1;
                splitpair(v.x, v.y, h0, l0);
                splitpair(v.z, v.w, h1, l1);
                *(uint2*)(sm + GHI + (row * GSTR + c) * 2) = make_uint2(h0, h1);
                *(uint2*)(sm + GLO + (row * GSTR + c) * 2) = make_uint2(l0, l1);
            }
        }
        // stage H (32 ch x 64 keys) from g_hpT [b][c][m]
        {
            int c = tid & 31, j0 = (tid >> 5) * 16;
            const float4* src = (const float4*)(g_hpT + ((size_t)(b * CQ + c)) * M3 + kb + j0);
#pragma unroll
            for (int i = 0; i < 4; i++) {
                float4 v = src[i];
                int j = j0 + i * 4;
                uint32_t h0, l0, h1, l1;
                splitpair(v.x, v.y, h0, l0);
                splitpair(v.z, v.w, h1, l1);
                *(uint2*)(sm + HHI + (c * HSTR + j) * 2) = make_uint2(h0, h1);
                *(uint2*)(sm + HLO + (c * HSTR + j) * 2) = make_uint2(l0, l1);
            }
        }
        __syncthreads();

#pragma unroll
        for (int rt = 0; rt < 2; rt++) {
            // ---- S GEMM: sacc[n][4] over 64 keys ----
            float sacc[8][4];
#pragma unroll
            for (int n = 0; n < 8; n++)
#pragma unroll
                for (int i = 0; i < 4; i++) sacc[n][i] = 0.f;

#pragma unroll
            for (int ks = 0; ks < 2; ks++) {
                uint32_t fh[4], fl[4];
                uint32_t fadr = smb + FHI + ((32 * w + 16 * rt + a_r) * FSTR + 16 * ks + a_c) * 2;
                ldsm4(fh, fadr);
                ldsm4(fl, fadr + FLO);
#pragma unroll
                for (int n = 0; n < 8; n++) {
                    uint32_t gh[2], gl[2];
                    uint32_t gadr = smb + GHI + ((8 * n + b_r) * GSTR + 16 * ks + b_c) * 2;
                    ldsm2(gh, gadr);
                    ldsm2(gl, gadr + (GLO - GHI));
                    mmabf(sacc[n], fh, gh);
                    mmabf(sacc[n], fl, gh);
                    mmabf(sacc[n], fh, gl);
                }
            }

            // ---- exp (base-2, scores pre-scaled) + l partials ----
#pragma unroll
            for (int n = 0; n < 8; n++) {
#pragma unroll
                for (int i = 0; i < 4; i++) sacc[n][i] = ex2f(sacc[n][i]);
                lpart[rt * 2 + 0] += sacc[n][0] + sacc[n][1];
                lpart[rt * 2 + 1] += sacc[n][2] + sacc[n][3];
            }

            // ---- PV GEMM: P from registers (hi/lo A-fragments) ----
#pragma unroll
            for (int ks = 0; ks < 4; ks++) {
                uint32_t ph[4], pl[4];
                splitpair(sacc[2 * ks][0],     sacc[2 * ks][1],     ph[0], pl[0]);
                splitpair(sacc[2 * ks][2],     sacc[2 * ks][3],     ph[1], pl[1]);
                splitpair(sacc[2 * ks + 1][0], sacc[2 * ks + 1][1], ph[2], pl[2]);
                splitpair(sacc[2 * ks + 1][2], sacc[2 * ks + 1][3], ph[3], pl[3]);
#pragma unroll
                for (int n2 = 0; n2 < 4; n2++) {
                    uint32_t hh[2], hl[2];
                    uint32_t hadr = smb + HHI + ((8 * n2 + b_r) * HSTR + 16 * ks + b_c) * 2;
                    ldsm2(hh, hadr);
                    ldsm2(hl, hadr + (HLO - HHI));
                    mmabf(oacc[rt][n2], ph, hh);
                    mmabf(oacc[rt][n2], pl, hh);
                    mmabf(oacc[rt][n2], ph, hl);
                }
            }
        }
    }

    // ---- reduce l across quad lanes ----
    float inv[4];
#pragma unroll
    for (int i = 0; i < 4; i++) {
        float v = lpart[i];
        v += __shfl_xor_sync(0xFFFFFFFFu, v, 1);
        v += __shfl_xor_sync(0xFFFFFFFFu, v, 2);
        inv[i] = 1.0f / v;
    }

    // ---- build normalized O A-fragments in registers ----
    uint32_t ofh[2][2][4], ofl[2][2][4];
#pragma unroll
    for (int rt = 0; rt < 2; rt++) {
        float i0 = inv[rt * 2 + 0], i1 = inv[rt * 2 + 1];
#pragma unroll
        for (int ks = 0; ks < 2; ks++) {
            splitpair(oacc[rt][2 * ks][0] * i0,     oacc[rt][2 * ks][1] * i0,     ofh[rt][ks][0], ofl[rt][ks][0]);
            splitpair(oacc[rt][2 * ks][2] * i1,     oacc[rt][2 * ks][3] * i1,     ofh[rt][ks][1], ofl[rt][ks][1]);
            splitpair(oacc[rt][2 * ks + 1][0] * i0, oacc[rt][2 * ks + 1][1] * i0, ofh[rt][ks][2], ofl[rt][ks][2]);
            splitpair(oacc[rt][2 * ks + 1][2] * i1, oacc[rt][2 * ks + 1][3] * i1, ofh[rt][ks][3], ofl[rt][ks][3]);
        }
    }

    // ---- stage Wv (overlays F/G/H) ----
    __syncthreads();
#pragma unroll
    for (int h = 0; h < 2; h++) {
        int r = tid + 128 * h;
        const float4* src = (const float4*)(Wv + r * CQ);
#pragma unroll
        for (int i = 0; i < 8; i++) {
            float4 v = src[i];
            int c = i * 4;
            uint32_t h0, l0, h1, l1;
            splitpair(v.x, v.y, h0, l0);
            splitpair(v.z, v.w, h1, l1);
            *(uint2*)(sm + WVH + (r * WSTR + c) * 2) = make_uint2(h0, h1);
            *(uint2*)(sm + WVL + (r * WSTR + c) * 2) = make_uint2(l0, l1);
        }
    }
    __syncthreads();

    // ---- Out = O(128x32) . Wv(256x32)^T in 4 chunks of 64 couts ----
#pragma unroll 1
    for (int ch = 0; ch < 4; ch++) {
        float wacc[2][8][4];
#pragma unroll
        for (int rt = 0; rt < 2; rt++)
#pragma unroll
            for (int n = 0; n < 8; n++)
#pragma unroll
                for (int i = 0; i < 4; i++) wacc[rt][n][i] = 0.f;

#pragma unroll
        for (int ks = 0; ks < 2; ks++) {
#pragma unroll
            for (int n = 0; n < 8; n++) {
                uint32_t wh[2], wl[2];
                uint32_t wadr = smb + WVH + ((ch * 64 + 8 * n + b_r) * WSTR + 16 * ks + b_c) * 2;
                ldsm2(wh, wadr);
                ldsm2(wl, wadr + WVL);
#pragma unroll
                for (int rt = 0; rt < 2; rt++) {
                    mmabf(wacc[rt][n], ofh[rt][ks], wh);
                    mmabf(wacc[rt][n], ofl[rt][ks], wh);
                    mmabf(wacc[rt][n], ofh[rt][ks], wl);
                }
            }
        }

        // write out + residual (out layout [b][c][n])
#pragma unroll
        for (int rt = 0; rt < 2; rt++) {
            int q0 = qbase + 32 * w + 16 * rt + (lane >> 2);
#pragma unroll
            for (int n = 0; n < 8; n++) {
                int cc = ch * 64 + 8 * n + 2 * (lane & 3);
                size_t o0 = ((size_t)(b * CIN + cc)) * N3 + q0;
                out[o0]          = fmaf(gma, wacc[rt][n][0], x[o0]);
                out[o0 + N3]     = fmaf(gma, wacc[rt][n][1], x[o0 + N3]);
                out[o0 + 8]      = fmaf(gma, wacc[rt][n][2], x[o0 + 8]);
                out[o0 + N3 + 8] = fmaf(gma, wacc[rt][n][3], x[o0 + N3 + 8]);
            }
        }
    }
}

// ---------------------------------------------------------------------------
extern "C" void kernel_launch(void* const* d_in, const int* in_sizes, int n_in,
                              void* d_out, int out_size)
{
    const float* x     = (const float*)d_in[0];
    const float* Wf    = (const float*)d_in[1];
    const float* Wg    = (const float*)d_in[2];
    const float* Wh    = (const float*)d_in[3];
    const float* Wv    = (const float*)d_in[4];
    const float* gamma = (const float*)d_in[5];
    float* out = (float*)d_out;

    dim3 pgrid(N3 / 128, B_);
    proj_mma_kernel<<<pgrid, 128>>>(x, Wf, Wg, Wh);

    int ptotal = B_ * CQ * M3;
    pool_kernel<<<(ptotal + 255) / 256, 256>>>();

    dim3 agrid(N3 / QT, B_);
    attn_mma_kernel<<<agrid, 128>>>(x, Wv, gamma, out);
}

// round 10
// speedup vs baseline: 2.6272x; 1.0012x over previous
#include <cuda_runtime.h>
#include <cuda_bf16.h>
#include <math.h>
#include <stdint.h>

#define B_   4
#define CIN  256
#define CQ   32
#define N3   13824   // 24^3
#define M3   1728    // 12^3
#define KT   64      // keys per tile
#define NKT  (M3/KT) // 27
#define QT   128     // queries per CTA

// ---- warp MMA helpers (baseline PTX, sm_75/80+ features) ----
__device__ __forceinline__ uint32_t smem_to_u32(const void* p) {
    uint32_t a;
    asm("{ .reg .u64 t; cvta.to.shared.u64 t, %1; cvt.u32.u64 %0, t; }" : "=r"(a) : "l"(p));
    return a;
}
__device__ __forceinline__ void ldsm4(uint32_t* r, uint32_t a) {
    asm volatile("ldmatrix.sync.aligned.m8n8.x4.shared.b16 {%0,%1,%2,%3}, [%4];"
        : "=r"(r[0]), "=r"(r[1]), "=r"(r[2]), "=r"(r[3]) : "r"(a));
}
__device__ __forceinline__ void ldsm2(uint32_t* r, uint32_t a) {
    asm volatile("ldmatrix.sync.aligned.m8n8.x2.shared.b16 {%0,%1}, [%2];"
        : "=r"(r[0]), "=r"(r[1]) : "r"(a));
}
__device__ __forceinline__ void ldsm2t(uint32_t* r, uint32_t a) {
    asm volatile("ldmatrix.sync.aligned.m8n8.x2.trans.shared.b16 {%0,%1}, [%2];"
        : "=r"(r[0]), "=r"(r[1]) : "r"(a));
}
__device__ __forceinline__ void mmabf(float* c, const uint32_t* a, const uint32_t* b) {
    asm volatile("mma.sync.aligned.m16n8k16.row.col.f32.bf16.bf16.f32 "
        "{%0,%1,%2,%3}, {%4,%5,%6,%7}, {%8,%9}, {%0,%1,%2,%3};"
        : "+f"(c[0]), "+f"(c[1]), "+f"(c[2]), "+f"(c[3])
        : "r"(a[0]), "r"(a[1]), "r"(a[2]), "r"(a[3]), "r"(b[0]), "r"(b[1]));
}
__device__ __forceinline__ float ex2f(float x) {
    float r; asm("ex2.approx.ftz.f32 %0, %1;" : "=f"(r) : "f"(x)); return r;
}
// split (a,b) -> bf16x2 hi reg + bf16x2 lo reg
__device__ __forceinline__ void splitpair(float a, float b, uint32_t& hi, uint32_t& lo) {
    __nv_bfloat162 h = __floats2bfloat162_rn(a, b);   // .x = a (low half)
    float ra = a - __bfloat162float(h.x);
    float rb = b - __bfloat162float(h.y);
    __nv_bfloat162 l = __floats2bfloat162_rn(ra, rb);
    hi = *(uint32_t*)&h;
    lo = *(uint32_t*)&l;
}

// Scratch (device globals). Layouts:
//   g_f, g_graw, g_hraw : [b][c][n]  (channel-major)
//   g_gp                : [b][m][c]
//   g_hpT               : [b][c][m]
__device__ float g_f[B_ * CQ * N3];
__device__ float g_graw[B_ * CQ * N3];
__device__ float g_hraw[B_ * CQ * N3];
__device__ float g_gp[B_ * M3 * CQ];
__device__ float g_hpT[B_ * CQ * M3];

// ---------------------------------------------------------------------------
// Projection via mma.sync: out[96, n] = W[96,256] x x[256, n] (3-term split).
// CTA: 128 positions, all 96 output channels. A = W (row-major), B = x chunk
// [k][n] consumed via ldmatrix.trans. Output channel-major [b][c][n].
// ---------------------------------------------------------------------------
#define PXSTR 272   // bytes per x row (128 bf16 + 8 pad)
#define PWSTR 80    // bytes per W row (32 bf16 + 8 pad)
#define PXHI 0
#define PXLO 8704
#define PWHI 17408
#define PWLO 25088
#define PSMEM 32768

__global__ __launch_bounds__(128) void proj_mma_kernel(
    const float* __restrict__ x,
    const float* __restrict__ Wf,
    const float* __restrict__ Wg,
    const float* __restrict__ Wh)
{
    __shared__ __align__(16) char sm[PSMEM];
    const uint32_t smb = smem_to_u32(sm);
    const int tid  = threadIdx.x;
    const int w    = tid >> 5;
    const int lane = tid & 31;
    const int b    = blockIdx.y;
    const int n0   = blockIdx.x * 128;

    const int a_r = lane & 15;
    const int a_c = (lane >> 4) << 3;
    const int tr  = (lane & 7) + 8 * ((lane >> 3) & 1);  // trans row id (lanes 0..15 used)

    float oacc[96];
#pragma unroll
    for (int i = 0; i < 96; i++) oacc[i] = 0.f;

    for (int cc0 = 0; cc0 < CIN; cc0 += 32) {
        __syncthreads();
        // stage x chunk [32 k][128 n] split hi/lo
#pragma unroll
        for (int i = 0; i < 8; i++) {
            int idx = tid + i * 128;        // 0..1023 float4 units
            int row = idx >> 5;
            int seg = idx & 31;
            float4 v = *(const float4*)(x + ((size_t)(b * CIN + cc0 + row)) * N3 + n0 + 4 * seg);
            uint32_t h0, l0, h1, l1;
            splitpair(v.x, v.y, h0, l0);
            splitpair(v.z, v.w, h1, l1);
            *(uint2*)(sm + PXHI + row * PXSTR + 8 * seg) = make_uint2(h0, h1);
            *(uint2*)(sm + PXLO + row * PXSTR + 8 * seg) = make_uint2(l0, l1);
        }
        // stage W chunk [96 rows][32 k] split hi/lo (rows 0-31 Wf, 32-63 Wg, 64-95 Wh)
#pragma unroll
        for (int i = 0; i < 6; i++) {
            int idx = tid + i * 128;        // 0..767 float4 units
            int row = idx >> 3;
            int seg = idx & 7;
            const float* Wsrc = (row < 32) ? Wf : ((row < 64) ? Wg : Wh);
            float4 v = *(const float4*)(Wsrc + (row & 31) * CIN + cc0 + 4 * seg);
            uint32_t h0, l0, h1, l1;
            splitpair(v.x, v.y, h0, l0);
            splitpair(v.z, v.w, h1, l1);
            *(uint2*)(sm + PWHI + row * PWSTR + 8 * seg) = make_uint2(h0, h1);
            *(uint2*)(sm + PWLO + row * PWSTR + 8 * seg) = make_uint2(l0, l1);
        }
        __syncthreads();

#pragma unroll
        for (int ks = 0; ks < 2; ks++) {
            // B frags from x via ldsm2.trans: warp w owns positions 32w..32w+31
            uint32_t bh[4][2], bl[4][2];
#pragma unroll
            for (int nt = 0; nt < 4; nt++) {
                uint32_t addr = smb + PXHI + (16 * ks + tr) * PXSTR + (32 * w + 8 * nt) * 2;
                ldsm2t(bh[nt], addr);
                ldsm2t(bl[nt], addr + (PXLO - PXHI));
            }
#pragma unroll
            for (int mt = 0; mt < 6; mt++) {
                uint32_t ah[4], al[4];
                uint32_t wadr = smb + PWHI + (16 * mt + a_r) * PWSTR + (16 * ks + a_c) * 2;
                ldsm4(ah, wadr);
                ldsm4(al, wadr + (PWLO - PWHI));
#pragma unroll
                for (int nt = 0; nt < 4; nt++) {
                    float* c = &oacc[(mt * 4 + nt) * 4];
                    mmabf(c, ah, bh[nt]);
                    mmabf(c, al, bh[nt]);
                    mmabf(c, ah, bl[nt]);
                }
            }
        }
    }

    // store: C[m=outch][n=pos], float2 per fragment row
    const int gid = lane >> 2;
    const int qid = lane & 3;
#pragma unroll
    for (int mt = 0; mt < 6; mt++) {
        float* dst = (mt < 2) ? g_f : ((mt < 4) ? g_graw : g_hraw);
        int ch = ((16 * mt) & 31) + gid;
#pragma unroll
        for (int nt = 0; nt < 4; nt++) {
            const float* c = &oacc[(mt * 4 + nt) * 4];
            int pos = n0 + 32 * w + 8 * nt + 2 * qid;
            size_t r0 = ((size_t)(b * CQ + ch)) * N3 + pos;
            size_t r1 = ((size_t)(b * CQ + ch + 8)) * N3 + pos;
            *(float2*)(dst + r0) = make_float2(c[0], c[1]);
            *(float2*)(dst + r1) = make_float2(c[2], c[3]);
        }
    }
}

// ---------------------------------------------------------------------------
// 2x2x2 max pool: [b][c][n] -> g_gp [b][m][c], g_hpT [b][c][m]
// ---------------------------------------------------------------------------
__global__ void pool_kernel()
{
    int idx = blockIdx.x * 256 + threadIdx.x;
    const int total = B_ * CQ * M3;
    if (idx >= total) return;
    int m = idx % M3;
    int c = (idx / M3) % CQ;
    int b = idx / (M3 * CQ);
    int md = m / 144, mh = (m / 12) % 12, mw = m % 12;

    const float* gbase = g_graw + ((size_t)(b * CQ + c)) * N3;
    const float* hbase = g_hraw + ((size_t)(b * CQ + c)) * N3;
    int n00 = (2 * md) * 576 + (2 * mh) * 24 + 2 * mw;

    float gmax = -INFINITY, hmax = -INFINITY;
#pragma unroll
    for (int dd = 0; dd < 2; dd++)
#pragma unroll
        for (int dh = 0; dh < 2; dh++) {
            int n = n00 + dd * 576 + dh * 24;
            float2 gv = *(const float2*)(gbase + n);
            float2 hv = *(const float2*)(hbase + n);
            gmax = fmaxf(gmax, fmaxf(gv.x, gv.y));
            hmax = fmaxf(hmax, fmaxf(hv.x, hv.y));
        }
    g_gp[((size_t)(b * M3 + m)) * CQ + c] = gmax;
    g_hpT[((size_t)(b * CQ + c)) * M3 + m] = hmax;
}

// ---------------------------------------------------------------------------
// Fused attention, register-resident P and O fragments.
// smem: F[128][40] hi/lo, G[64][40] hi/lo, H[32][72] hi/lo; Wv overlays after.
// ---------------------------------------------------------------------------
#define FSTR 40
#define GSTR 40
#define HSTR 72
#define WSTR 40
#define FHI 0
#define FLO 10240
#define GHI 20480
#define GLO 25600
#define HHI 30720
#define HLO 35328
#define WVH 0
#define WVL 20480
#define ASMEM 40960

__global__ __launch_bounds__(128) void attn_mma_kernel(
    const float* __restrict__ x,
    const float* __restrict__ Wv,
    const float* __restrict__ gamma_p,
    float* __restrict__ out)
{
    __shared__ __align__(16) char sm[ASMEM];
    const uint32_t smb = smem_to_u32(sm);
    const int tid  = threadIdx.x;
    const int w    = tid >> 5;
    const int lane = tid & 31;
    const int b = blockIdx.y;
    const int qbase = blockIdx.x * QT;

    const float gma = *gamma_p;
    const float LOG2E = 1.4426950408889634f;

    const int a_r = lane & 15;
    const int a_c = (lane >> 4) << 3;
    const int b_r = lane & 7;
    const int b_c = ((lane >> 3) & 1) << 3;

    // ---- load F tile from [b][c][n], fold log2e ----
    {
        const float* fb = g_f + (size_t)b * CQ * N3 + qbase + tid;
#pragma unroll
        for (int cp = 0; cp < 16; cp++) {
            float fa = fb[(size_t)(2 * cp) * N3] * LOG2E;
            float fc = fb[(size_t)(2 * cp + 1) * N3] * LOG2E;
            uint32_t h, l;
            splitpair(fa, fc, h, l);
            *(uint32_t*)(sm + FHI + (tid * FSTR + 2 * cp) * 2) = h;
            *(uint32_t*)(sm + FLO + (tid * FSTR + 2 * cp) * 2) = l;
        }
    }

    float oacc[2][4][4];
#pragma unroll
    for (int rt = 0; rt < 2; rt++)
#pragma unroll
        for (int n = 0; n < 4; n++)
#pragma unroll
            for (int i = 0; i < 4; i++) oacc[rt][n][i] = 0.f;
    float lpart[4] = {0.f, 0.f, 0.f, 0.f};

    for (int kt = 0; kt < NKT; kt++) {
        const int kb = kt * KT;
        __syncthreads();
        // stage G (64 keys x 32 ch) from g_gp [b][m][c]
        {
            int row = tid & 63, half = tid >> 6;
            const float4* src = (const float4*)(g_gp + ((size_t)(b * M3 + kb + row)) * CQ + 16 * half);
#pragma unroll
            for (int i = 0; i < 4; i++) {
                float4 v = src[i];
                int c = 16 * half + i * 4;
                uint32_t h0, l0, h1, l1;
                splitpair(v.x, v.y, h0, l0);
                splitpair(v.z, v.w, h1, l1);
                *(uint2*)(sm + GHI + (row * GSTR + c) * 2) = make_uint2(h0, h1);
                *(uint2*)(sm + GLO + (row * GSTR + c) * 2) = make_uint2(l0, l1);
            }
        }
        // stage H (32 ch x 64 keys) from g_hpT [b][c][m]
        {
            int c = tid & 31, j0 = (tid >> 5) * 16;
            const float4* src = (const float4*)(g_hpT + ((size_t)(b * CQ + c)) * M3 + kb + j0);
#pragma unroll
            for (int i = 0; i < 4; i++) {
                float4 v = src[i];
                int j = j0 + i * 4;
                uint32_t h0, l0, h1, l1;
                splitpair(v.x, v.y, h0, l0);
                splitpair(v.z, v.w, h1, l1);
                *(uint2*)(sm + HHI + (c * HSTR + j) * 2) = make_uint2(h0, h1);
                *(uint2*)(sm + HLO + (c * HSTR + j) * 2) = make_uint2(l0, l1);
            }
        }
        __syncthreads();

#pragma unroll
        for (int rt = 0; rt < 2; rt++) {
            // ---- S GEMM: sacc[n][4] over 64 keys ----
            float sacc[8][4];
#pragma unroll
            for (int n = 0; n < 8; n++)
#pragma unroll
                for (int i = 0; i < 4; i++) sacc[n][i] = 0.f;

#pragma unroll
            for (int ks = 0; ks < 2; ks++) {
                uint32_t fh[4], fl[4];
                uint32_t fadr = smb + FHI + ((32 * w + 16 * rt + a_r) * FSTR + 16 * ks + a_c) * 2;
                ldsm4(fh, fadr);
                ldsm4(fl, fadr + FLO);
#pragma unroll
                for (int n = 0; n < 8; n++) {
                    uint32_t gh[2], gl[2];
                    uint32_t gadr = smb + GHI + ((8 * n + b_r) * GSTR + 16 * ks + b_c) * 2;
                    ldsm2(gh, gadr);
                    ldsm2(gl, gadr + (GLO - GHI));
                    mmabf(sacc[n], fh, gh);
                    mmabf(sacc[n], fl, gh);
                    mmabf(sacc[n], fh, gl);
                }
            }

            // ---- exp (base-2, scores pre-scaled) + l partials ----
#pragma unroll
            for (int n = 0; n < 8; n++) {
#pragma unroll
                for (int i = 0; i < 4; i++) sacc[n][i] = ex2f(sacc[n][i]);
                lpart[rt * 2 + 0] += sacc[n][0] + sacc[n][1];
                lpart[rt * 2 + 1] += sacc[n][2] + sacc[n][3];
            }

            // ---- PV GEMM: P from registers (hi/lo A-fragments) ----
#pragma unroll
            for (int ks = 0; ks < 4; ks++) {
                uint32_t ph[4], pl[4];
                splitpair(sacc[2 * ks][0],     sacc[2 * ks][1],     ph[0], pl[0]);
                splitpair(sacc[2 * ks][2],     sacc[2 * ks][3],     ph[1], pl[1]);
                splitpair(sacc[2 * ks + 1][0], sacc[2 * ks + 1][1], ph[2], pl[2]);
                splitpair(sacc[2 * ks + 1][2], sacc[2 * ks + 1][3], ph[3], pl[3]);
#pragma unroll
                for (int n2 = 0; n2 < 4; n2++) {
                    uint32_t hh[2], hl[2];
                    uint32_t hadr = smb + HHI + ((8 * n2 + b_r) * HSTR + 16 * ks + b_c) * 2;
                    ldsm2(hh, hadr);
                    ldsm2(hl, hadr + (HLO - HHI));
                    mmabf(oacc[rt][n2], ph, hh);
                    mmabf(oacc[rt][n2], pl, hh);
                    mmabf(oacc[rt][n2], ph, hl);
                }
            }
        }
    }

    // ---- reduce l across quad lanes ----
    float inv[4];
#pragma unroll
    for (int i = 0; i < 4; i++) {
        float v = lpart[i];
        v += __shfl_xor_sync(0xFFFFFFFFu, v, 1);
        v += __shfl_xor_sync(0xFFFFFFFFu, v, 2);
        inv[i] = 1.0f / v;
    }

    // ---- build normalized O A-fragments in registers ----
    uint32_t ofh[2][2][4], ofl[2][2][4];
#pragma unroll
    for (int rt = 0; rt < 2; rt++) {
        float i0 = inv[rt * 2 + 0], i1 = inv[rt * 2 + 1];
#pragma unroll
        for (int ks = 0; ks < 2; ks++) {
            splitpair(oacc[rt][2 * ks][0] * i0,     oacc[rt][2 * ks][1] * i0,     ofh[rt][ks][0], ofl[rt][ks][0]);
            splitpair(oacc[rt][2 * ks][2] * i1,     oacc[rt][2 * ks][3] * i1,     ofh[rt][ks][1], ofl[rt][ks][1]);
            splitpair(oacc[rt][2 * ks + 1][0] * i0, oacc[rt][2 * ks + 1][1] * i0, ofh[rt][ks][2], ofl[rt][ks][2]);
            splitpair(oacc[rt][2 * ks + 1][2] * i1, oacc[rt][2 * ks + 1][3] * i1, ofh[rt][ks][3], ofl[rt][ks][3]);
        }
    }

    // ---- stage Wv (overlays F/G/H) ----
    __syncthreads();
#pragma unroll
    for (int h = 0; h < 2; h++) {
        int r = tid + 128 * h;
        const float4* src = (const float4*)(Wv + r * CQ);
#pragma unroll
        for (int i = 0; i < 8; i++) {
            float4 v = src[i];
            int c = i * 4;
            uint32_t h0, l0, h1, l1;
            splitpair(v.x, v.y, h0, l0);
            splitpair(v.z, v.w, h1, l1);
            *(uint2*)(sm + WVH + (r * WSTR + c) * 2) = make_uint2(h0, h1);
            *(uint2*)(sm + WVL + (r * WSTR + c) * 2) = make_uint2(l0, l1);
        }
    }
    __syncthreads();

    // ---- Out = O(128x32) . Wv(256x32)^T in 4 chunks of 64 couts ----
#pragma unroll 1
    for (int ch = 0; ch < 4; ch++) {
        float wacc[2][8][4];
#pragma unroll
        for (int rt = 0; rt < 2; rt++)
#pragma unroll
            for (int n = 0; n < 8; n++)
#pragma unroll
                for (int i = 0; i < 4; i++) wacc[rt][n][i] = 0.f;

#pragma unroll
        for (int ks = 0; ks < 2; ks++) {
#pragma unroll
            for (int n = 0; n < 8; n++) {
                uint32_t wh[2], wl[2];
                uint32_t wadr = smb + WVH + ((ch * 64 + 8 * n + b_r) * WSTR + 16 * ks + b_c) * 2;
                ldsm2(wh, wadr);
                ldsm2(wl, wadr + WVL);
#pragma unroll
                for (int rt = 0; rt < 2; rt++) {
                    mmabf(wacc[rt][n], ofh[rt][ks], wh);
                    mmabf(wacc[rt][n], ofl[rt][ks], wh);
                    mmabf(wacc[rt][n], ofh[rt][ks], wl);
                }
            }
        }

        // write out + residual (out layout [b][c][n])
#pragma unroll
        for (int rt = 0; rt < 2; rt++) {
            int q0 = qbase + 32 * w + 16 * rt + (lane >> 2);
#pragma unroll
            for (int n = 0; n < 8; n++) {
                int cc = ch * 64 + 8 * n + 2 * (lane & 3);
                size_t o0 = ((size_t)(b * CIN + cc)) * N3 + q0;
                out[o0]          = fmaf(gma, wacc[rt][n][0], x[o0]);
                out[o0 + N3]     = fmaf(gma, wacc[rt][n][1], x[o0 + N3]);
                out[o0 + 8]      = fmaf(gma, wacc[rt][n][2], x[o0 + 8]);
                out[o0 + N3 + 8] = fmaf(gma, wacc[rt][n][3], x[o0 + N3 + 8]);
            }
        }
    }
}

// ---------------------------------------------------------------------------
extern "C" void kernel_launch(void* const* d_in, const int* in_sizes, int n_in,
                              void* d_out, int out_size)
{
    const float* x     = (const float*)d_in[0];
    const float* Wf    = (const float*)d_in[1];
    const float* Wg    = (const float*)d_in[2];
    const float* Wh    = (const float*)d_in[3];
    const float* Wv    = (const float*)d_in[4];
    const float* gamma = (const float*)d_in[5];
    float* out = (float*)d_out;

    dim3 pgrid(N3 / 128, B_);
    proj_mma_kernel<<<pgrid, 128>>>(x, Wf, Wg, Wh);

    int ptotal = B_ * CQ * M3;
    pool_kernel<<<(ptotal + 255) / 256, 256>>>();

    dim3 agrid(N3 / QT, B_);
    attn_mma_kernel<<<agrid, 128>>>(x, Wv, gamma, out);
}

// round 11
// speedup vs baseline: 2.6290x; 1.0007x over previous
#include <cuda_runtime.h>
#include <cuda_bf16.h>
#include <math.h>
#include <stdint.h>

#define B_   4
#define CIN  256
#define CQ   32
#define N3   13824   // 24^3
#define M3   1728    // 12^3
#define KT   64      // keys per tile
#define NKT  (M3/KT) // 27
#define QT   128     // queries per CTA

// ---- warp MMA helpers (baseline PTX, sm_75/80+ features) ----
__device__ __forceinline__ uint32_t smem_to_u32(const void* p) {
    uint32_t a;
    asm("{ .reg .u64 t; cvta.to.shared.u64 t, %1; cvt.u32.u64 %0, t; }" : "=r"(a) : "l"(p));
    return a;
}
__device__ __forceinline__ void ldsm4(uint32_t* r, uint32_t a) {
    asm volatile("ldmatrix.sync.aligned.m8n8.x4.shared.b16 {%0,%1,%2,%3}, [%4];"
        : "=r"(r[0]), "=r"(r[1]), "=r"(r[2]), "=r"(r[3]) : "r"(a));
}
__device__ __forceinline__ void ldsm2(uint32_t* r, uint32_t a) {
    asm volatile("ldmatrix.sync.aligned.m8n8.x2.shared.b16 {%0,%1}, [%2];"
        : "=r"(r[0]), "=r"(r[1]) : "r"(a));
}
__device__ __forceinline__ void ldsm2t(uint32_t* r, uint32_t a) {
    asm volatile("ldmatrix.sync.aligned.m8n8.x2.trans.shared.b16 {%0,%1}, [%2];"
        : "=r"(r[0]), "=r"(r[1]) : "r"(a));
}
__device__ __forceinline__ void mmabf(float* c, const uint32_t* a, const uint32_t* b) {
    asm volatile("mma.sync.aligned.m16n8k16.row.col.f32.bf16.bf16.f32 "
        "{%0,%1,%2,%3}, {%4,%5,%6,%7}, {%8,%9}, {%0,%1,%2,%3};"
        : "+f"(c[0]), "+f"(c[1]), "+f"(c[2]), "+f"(c[3])
        : "r"(a[0]), "r"(a[1]), "r"(a[2]), "r"(a[3]), "r"(b[0]), "r"(b[1]));
}
__device__ __forceinline__ float ex2f(float x) {
    float r; asm("ex2.approx.ftz.f32 %0, %1;" : "=f"(r) : "f"(x)); return r;
}
// split (a,b) -> bf16x2 hi reg + bf16x2 lo reg
__device__ __forceinline__ void splitpair(float a, float b, uint32_t& hi, uint32_t& lo) {
    __nv_bfloat162 h = __floats2bfloat162_rn(a, b);   // .x = a (low half)
    float ra = a - __bfloat162float(h.x);
    float rb = b - __bfloat162float(h.y);
    __nv_bfloat162 l = __floats2bfloat162_rn(ra, rb);
    hi = *(uint32_t*)&h;
    lo = *(uint32_t*)&l;
}

// Scratch (device globals). Layouts:
//   g_f, g_graw, g_hraw : [b][c][n]  (channel-major)
//   g_gp                : [b][m][c]
//   g_hpT               : [b][c][m]
__device__ float g_f[B_ * CQ * N3];
__device__ float g_graw[B_ * CQ * N3];
__device__ float g_hraw[B_ * CQ * N3];
__device__ float g_gp[B_ * M3 * CQ];
__device__ float g_hpT[B_ * CQ * M3];

// ---------------------------------------------------------------------------
// Projection via mma.sync: out[96, n] = W[96,256] x x[256, n] (3-term split).
// CTA: 128 positions, all 96 output channels. A = W (row-major), B = x chunk
// [k][n] consumed via ldmatrix.trans. Output channel-major [b][c][n].
// ---------------------------------------------------------------------------
#define PXSTR 272   // bytes per x row (128 bf16 + 8 pad)
#define PWSTR 80    // bytes per W row (32 bf16 + 8 pad)
#define PXHI 0
#define PXLO 8704
#define PWHI 17408
#define PWLO 25088
#define PSMEM 32768

__global__ __launch_bounds__(128) void proj_mma_kernel(
    const float* __restrict__ x,
    const float* __restrict__ Wf,
    const float* __restrict__ Wg,
    const float* __restrict__ Wh)
{
    __shared__ __align__(16) char sm[PSMEM];
    const uint32_t smb = smem_to_u32(sm);
    const int tid  = threadIdx.x;
    const int w    = tid >> 5;
    const int lane = tid & 31;
    const int b    = blockIdx.y;
    const int n0   = blockIdx.x * 128;

    const int a_r = lane & 15;
    const int a_c = (lane >> 4) << 3;
    const int tr  = (lane & 7) + 8 * ((lane >> 3) & 1);  // trans row id (lanes 0..15 used)

    float oacc[96];
#pragma unroll
    for (int i = 0; i < 96; i++) oacc[i] = 0.f;

    for (int cc0 = 0; cc0 < CIN; cc0 += 32) {
        __syncthreads();
        // stage x chunk [32 k][128 n] split hi/lo
#pragma unroll
        for (int i = 0; i < 8; i++) {
            int idx = tid + i * 128;        // 0..1023 float4 units
            int row = idx >> 5;
            int seg = idx & 31;
            float4 v = *(const float4*)(x + ((size_t)(b * CIN + cc0 + row)) * N3 + n0 + 4 * seg);
            uint32_t h0, l0, h1, l1;
            splitpair(v.x, v.y, h0, l0);
            splitpair(v.z, v.w, h1, l1);
            *(uint2*)(sm + PXHI + row * PXSTR + 8 * seg) = make_uint2(h0, h1);
            *(uint2*)(sm + PXLO + row * PXSTR + 8 * seg) = make_uint2(l0, l1);
        }
        // stage W chunk [96 rows][32 k] split hi/lo (rows 0-31 Wf, 32-63 Wg, 64-95 Wh)
#pragma unroll
        for (int i = 0; i < 6; i++) {
            int idx = tid + i * 128;        // 0..767 float4 units
            int row = idx >> 3;
            int seg = idx & 7;
            const float* Wsrc = (row < 32) ? Wf : ((row < 64) ? Wg : Wh);
            float4 v = *(const float4*)(Wsrc + (row & 31) * CIN + cc0 + 4 * seg);
            uint32_t h0, l0, h1, l1;
            splitpair(v.x, v.y, h0, l0);
            splitpair(v.z, v.w, h1, l1);
            *(uint2*)(sm + PWHI + row * PWSTR + 8 * seg) = make_uint2(h0, h1);
            *(uint2*)(sm + PWLO + row * PWSTR + 8 * seg) = make_uint2(l0, l1);
        }
        __syncthreads();

#pragma unroll
        for (int ks = 0; ks < 2; ks++) {
            // B frags from x via ldsm2.trans: warp w owns positions 32w..32w+31
            uint32_t bh[4][2], bl[4][2];
#pragma unroll
            for (int nt = 0; nt < 4; nt++) {
                uint32_t addr = smb + PXHI + (16 * ks + tr) * PXSTR + (32 * w + 8 * nt) * 2;
                ldsm2t(bh[nt], addr);
                ldsm2t(bl[nt], addr + (PXLO - PXHI));
            }
#pragma unroll
            for (int mt = 0; mt < 6; mt++) {
                uint32_t ah[4], al[4];
                uint32_t wadr = smb + PWHI + (16 * mt + a_r) * PWSTR + (16 * ks + a_c) * 2;
                ldsm4(ah, wadr);
                ldsm4(al, wadr + (PWLO - PWHI));
#pragma unroll
                for (int nt = 0; nt < 4; nt++) {
                    float* c = &oacc[(mt * 4 + nt) * 4];
                    mmabf(c, ah, bh[nt]);
                    mmabf(c, al, bh[nt]);
                    mmabf(c, ah, bl[nt]);
                }
            }
        }
    }

    // store: C[m=outch][n=pos], float2 per fragment row
    const int gid = lane >> 2;
    const int qid = lane & 3;
#pragma unroll
    for (int mt = 0; mt < 6; mt++) {
        float* dst = (mt < 2) ? g_f : ((mt < 4) ? g_graw : g_hraw);
        int ch = ((16 * mt) & 31) + gid;
#pragma unroll
        for (int nt = 0; nt < 4; nt++) {
            const float* c = &oacc[(mt * 4 + nt) * 4];
            int pos = n0 + 32 * w + 8 * nt + 2 * qid;
            size_t r0 = ((size_t)(b * CQ + ch)) * N3 + pos;
            size_t r1 = ((size_t)(b * CQ + ch + 8)) * N3 + pos;
            *(float2*)(dst + r0) = make_float2(c[0], c[1]);
            *(float2*)(dst + r1) = make_float2(c[2], c[3]);
        }
    }
}

// ---------------------------------------------------------------------------
// 2x2x2 max pool: [b][c][n] -> g_gp [b][m][c], g_hpT [b][c][m]
// ---------------------------------------------------------------------------
__global__ void pool_kernel()
{
    int idx = blockIdx.x * 256 + threadIdx.x;
    const int total = B_ * CQ * M3;
    if (idx >= total) return;
    int m = idx % M3;
    int c = (idx / M3) % CQ;
    int b = idx / (M3 * CQ);
    int md = m / 144, mh = (m / 12) % 12, mw = m % 12;

    const float* gbase = g_graw + ((size_t)(b * CQ + c)) * N3;
    const float* hbase = g_hraw + ((size_t)(b * CQ + c)) * N3;
    int n00 = (2 * md) * 576 + (2 * mh) * 24 + 2 * mw;

    float gmax = -INFINITY, hmax = -INFINITY;
#pragma unroll
    for (int dd = 0; dd < 2; dd++)
#pragma unroll
        for (int dh = 0; dh < 2; dh++) {
            int n = n00 + dd * 576 + dh * 24;
            float2 gv = *(const float2*)(gbase + n);
            float2 hv = *(const float2*)(hbase + n);
            gmax = fmaxf(gmax, fmaxf(gv.x, gv.y));
            hmax = fmaxf(hmax, fmaxf(hv.x, hv.y));
        }
    g_gp[((size_t)(b * M3 + m)) * CQ + c] = gmax;
    g_hpT[((size_t)(b * CQ + c)) * M3 + m] = hmax;
}

// ---------------------------------------------------------------------------
// Fused attention, register-resident P and O fragments.
// smem: F[128][40] hi/lo, G[64][40] hi/lo, H[32][72] hi/lo; Wv overlays after.
// ---------------------------------------------------------------------------
#define FSTR 40
#define GSTR 40
#define HSTR 72
#define WSTR 40
#define FHI 0
#define FLO 10240
#define GHI 20480
#define GLO 25600
#define HHI 30720
#define HLO 35328
#define WVH 0
#define WVL 20480
#define ASMEM 40960

__global__ __launch_bounds__(128) void attn_mma_kernel(
    const float* __restrict__ x,
    const float* __restrict__ Wv,
    const float* __restrict__ gamma_p,
    float* __restrict__ out)
{
    __shared__ __align__(16) char sm[ASMEM];
    const uint32_t smb = smem_to_u32(sm);
    const int tid  = threadIdx.x;
    const int w    = tid >> 5;
    const int lane = tid & 31;
    const int b = blockIdx.y;
    const int qbase = blockIdx.x * QT;

    const float gma = *gamma_p;
    const float LOG2E = 1.4426950408889634f;

    const int a_r = lane & 15;
    const int a_c = (lane >> 4) << 3;
    const int b_r = lane & 7;
    const int b_c = ((lane >> 3) & 1) << 3;

    // ---- load F tile from [b][c][n], fold log2e ----
    {
        const float* fb = g_f + (size_t)b * CQ * N3 + qbase + tid;
#pragma unroll
        for (int cp = 0; cp < 16; cp++) {
            float fa = fb[(size_t)(2 * cp) * N3] * LOG2E;
            float fc = fb[(size_t)(2 * cp + 1) * N3] * LOG2E;
            uint32_t h, l;
            splitpair(fa, fc, h, l);
            *(uint32_t*)(sm + FHI + (tid * FSTR + 2 * cp) * 2) = h;
            *(uint32_t*)(sm + FLO + (tid * FSTR + 2 * cp) * 2) = l;
        }
    }

    float oacc[2][4][4];
#pragma unroll
    for (int rt = 0; rt < 2; rt++)
#pragma unroll
        for (int n = 0; n < 4; n++)
#pragma unroll
            for (int i = 0; i < 4; i++) oacc[rt][n][i] = 0.f;
    float lpart[4] = {0.f, 0.f, 0.f, 0.f};

    for (int kt = 0; kt < NKT; kt++) {
        const int kb = kt * KT;
        __syncthreads();
        // stage G (64 keys x 32 ch) from g_gp [b][m][c]
        {
            int row = tid & 63, half = tid >> 6;
            const float4* src = (const float4*)(g_gp + ((size_t)(b * M3 + kb + row)) * CQ + 16 * half);
#pragma unroll
            for (int i = 0; i < 4; i++) {
                float4 v = src[i];
                int c = 16 * half + i * 4;
                uint32_t h0, l0, h1, l1;
                splitpair(v.x, v.y, h0, l0);
                splitpair(v.z, v.w, h1, l1);
                *(uint2*)(sm + GHI + (row * GSTR + c) * 2) = make_uint2(h0, h1);
                *(uint2*)(sm + GLO + (row * GSTR + c) * 2) = make_uint2(l0, l1);
            }
        }
        // stage H (32 ch x 64 keys) from g_hpT [b][c][m]
        {
            int c = tid & 31, j0 = (tid >> 5) * 16;
            const float4* src = (const float4*)(g_hpT + ((size_t)(b * CQ + c)) * M3 + kb + j0);
#pragma unroll
            for (int i = 0; i < 4; i++) {
                float4 v = src[i];
                int j = j0 + i * 4;
                uint32_t h0, l0, h1, l1;
                splitpair(v.x, v.y, h0, l0);
                splitpair(v.z, v.w, h1, l1);
                *(uint2*)(sm + HHI + (c * HSTR + j) * 2) = make_uint2(h0, h1);
                *(uint2*)(sm + HLO + (c * HSTR + j) * 2) = make_uint2(l0, l1);
            }
        }
        __syncthreads();

#pragma unroll
        for (int rt = 0; rt < 2; rt++) {
            // ---- S GEMM: sacc[n][4] over 64 keys ----
            float sacc[8][4];
#pragma unroll
            for (int n = 0; n < 8; n++)
#pragma unroll
                for (int i = 0; i < 4; i++) sacc[n][i] = 0.f;

#pragma unroll
            for (int ks = 0; ks < 2; ks++) {
                uint32_t fh[4], fl[4];
                uint32_t fadr = smb + FHI + ((32 * w + 16 * rt + a_r) * FSTR + 16 * ks + a_c) * 2;
                ldsm4(fh, fadr);
                ldsm4(fl, fadr + FLO);
#pragma unroll
                for (int n = 0; n < 8; n++) {
                    uint32_t gh[2], gl[2];
                    uint32_t gadr = smb + GHI + ((8 * n + b_r) * GSTR + 16 * ks + b_c) * 2;
                    ldsm2(gh, gadr);
                    ldsm2(gl, gadr + (GLO - GHI));
                    mmabf(sacc[n], fh, gh);
                    mmabf(sacc[n], fl, gh);
                    mmabf(sacc[n], fh, gl);
                }
            }

            // ---- exp (base-2, scores pre-scaled) + l partials ----
#pragma unroll
            for (int n = 0; n < 8; n++) {
#pragma unroll
                for (int i = 0; i < 4; i++) sacc[n][i] = ex2f(sacc[n][i]);
                lpart[rt * 2 + 0] += sacc[n][0] + sacc[n][1];
                lpart[rt * 2 + 1] += sacc[n][2] + sacc[n][3];
            }

            // ---- PV GEMM: P from registers (hi/lo A-fragments) ----
#pragma unroll
            for (int ks = 0; ks < 4; ks++) {
                uint32_t ph[4], pl[4];
                splitpair(sacc[2 * ks][0],     sacc[2 * ks][1],     ph[0], pl[0]);
                splitpair(sacc[2 * ks][2],     sacc[2 * ks][3],     ph[1], pl[1]);
                splitpair(sacc[2 * ks + 1][0], sacc[2 * ks + 1][1], ph[2], pl[2]);
                splitpair(sacc[2 * ks + 1][2], sacc[2 * ks + 1][3], ph[3], pl[3]);
#pragma unroll
                for (int n2 = 0; n2 < 4; n2++) {
                    uint32_t hh[2], hl[2];
                    uint32_t hadr = smb + HHI + ((8 * n2 + b_r) * HSTR + 16 * ks + b_c) * 2;
                    ldsm2(hh, hadr);
                    ldsm2(hl, hadr + (HLO - HHI));
                    mmabf(oacc[rt][n2], ph, hh);
                    mmabf(oacc[rt][n2], pl, hh);
                    mmabf(oacc[rt][n2], ph, hl);
                }
            }
        }
    }

    // ---- reduce l across quad lanes ----
    float inv[4];
#pragma unroll
    for (int i = 0; i < 4; i++) {
        float v = lpart[i];
        v += __shfl_xor_sync(0xFFFFFFFFu, v, 1);
        v += __shfl_xor_sync(0xFFFFFFFFu, v, 2);
        inv[i] = 1.0f / v;
    }

    // ---- build normalized O A-fragments in registers ----
    uint32_t ofh[2][2][4], ofl[2][2][4];
#pragma unroll
    for (int rt = 0; rt < 2; rt++) {
        float i0 = inv[rt * 2 + 0], i1 = inv[rt * 2 + 1];
#pragma unroll
        for (int ks = 0; ks < 2; ks++) {
            splitpair(oacc[rt][2 * ks][0] * i0,     oacc[rt][2 * ks][1] * i0,     ofh[rt][ks][0], ofl[rt][ks][0]);
            splitpair(oacc[rt][2 * ks][2] * i1,     oacc[rt][2 * ks][3] * i1,     ofh[rt][ks][1], ofl[rt][ks][1]);
            splitpair(oacc[rt][2 * ks + 1][0] * i0, oacc[rt][2 * ks + 1][1] * i0, ofh[rt][ks][2], ofl[rt][ks][2]);
            splitpair(oacc[rt][2 * ks + 1][2] * i1, oacc[rt][2 * ks + 1][3] * i1, ofh[rt][ks][3], ofl[rt][ks][3]);
        }
    }

    // ---- stage Wv (overlays F/G/H) ----
    __syncthreads();
#pragma unroll
    for (int h = 0; h < 2; h++) {
        int r = tid + 128 * h;
        const float4* src = (const float4*)(Wv + r * CQ);
#pragma unroll
        for (int i = 0; i < 8; i++) {
            float4 v = src[i];
            int c = i * 4;
            uint32_t h0, l0, h1, l1;
            splitpair(v.x, v.y, h0, l0);
            splitpair(v.z, v.w, h1, l1);
            *(uint2*)(sm + WVH + (r * WSTR + c) * 2) = make_uint2(h0, h1);
            *(uint2*)(sm + WVL + (r * WSTR + c) * 2) = make_uint2(l0, l1);
        }
    }
    __syncthreads();

    // ---- Out = O(128x32) . Wv(256x32)^T in 4 chunks of 64 couts ----
#pragma unroll 1
    for (int ch = 0; ch < 4; ch++) {
        float wacc[2][8][4];
#pragma unroll
        for (int rt = 0; rt < 2; rt++)
#pragma unroll
            for (int n = 0; n < 8; n++)
#pragma unroll
                for (int i = 0; i < 4; i++) wacc[rt][n][i] = 0.f;

#pragma unroll
        for (int ks = 0; ks < 2; ks++) {
#pragma unroll
            for (int n = 0; n < 8; n++) {
                uint32_t wh[2], wl[2];
                uint32_t wadr = smb + WVH + ((ch * 64 + 8 * n + b_r) * WSTR + 16 * ks + b_c) * 2;
                ldsm2(wh, wadr);
                ldsm2(wl, wadr + WVL);
#pragma unroll
                for (int rt = 0; rt < 2; rt++) {
                    mmabf(wacc[rt][n], ofh[rt][ks], wh);
                    mmabf(wacc[rt][n], ofl[rt][ks], wh);
                    mmabf(wacc[rt][n], ofh[rt][ks], wl);
                }
            }
        }

        // write out + residual (out layout [b][c][n])
#pragma unroll
        for (int rt = 0; rt < 2; rt++) {
            int q0 = qbase + 32 * w + 16 * rt + (lane >> 2);
#pragma unroll
            for (int n = 0; n < 8; n++) {
                int cc = ch * 64 + 8 * n + 2 * (lane & 3);
                size_t o0 = ((size_t)(b * CIN + cc)) * N3 + q0;
                out[o0]          = fmaf(gma, wacc[rt][n][0], x[o0]);
                out[o0 + N3]     = fmaf(gma, wacc[rt][n][1], x[o0 + N3]);
                out[o0 + 8]      = fmaf(gma, wacc[rt][n][2], x[o0 + 8]);
                out[o0 + N3 + 8] = fmaf(gma, wacc[rt][n][3], x[o0 + N3 + 8]);
            }
        }
    }
}

// ---------------------------------------------------------------------------
extern "C" void kernel_launch(void* const* d_in, const int* in_sizes, int n_in,
                              void* d_out, int out_size)
{
    const float* x     = (const float*)d_in[0];
    const float* Wf    = (const float*)d_in[1];
    const float* Wg    = (const float*)d_in[2];
    const float* Wh    = (const float*)d_in[3];
    const float* Wv    = (const float*)d_in[4];
    const float* gamma = (const float*)d_in[5];
    float* out = (float*)d_out;

    dim3 pgrid(N3 / 128, B_);
    proj_mma_kernel<<<pgrid, 128>>>(x, Wf, Wg, Wh);

    int ptotal = B_ * CQ * M3;
    pool_kernel<<<(ptotal + 255) / 256, 256>>>();

    dim3 agrid(N3 / QT, B_);
    attn_mma_kernel<<<agrid, 128>>>(x, Wv, gamma, out);
}